// round 15
// baseline (speedup 1.0000x reference)
#include <cuda_runtime.h>
#include <cuda_fp16.h>
#include <math.h>
#include <stdint.h>

#define NN 100000
#define EE 1600000
#define BB 64
#define LN_EPS 1e-5f

// ---------------- scratch ----------------
static __device__ int    g_deg[NN];
static __device__ int    g_rowstart[NN + 1];
static __device__ int    g_wptr[NN];
static __device__ float  g_dis[NN];
static __device__ float  g_selfw[NN];
static __device__ int2   g_edge8[EE];         // {src, half2(ea0,ea1)} (convs)
static __device__ int    g_esrc[EE];          // src only (APPNP)
static __device__ __half g_x16[NN * 64];
static __device__ __half g_t0h[NN * 64];
static __device__ __half g_hBh[NN * 128];     // conv2 out -> mlp2 in -> APPNP pong
static __device__ __half g_h16A[NN * 128];    // u ping
static __device__ __half g_h16B[NN * 128];    // y0
static __device__ __half g_x0h[NN * 128];     // mlp2 out (h0 = x0), kept intact
static __device__ __half g_w1ah[64 * 128];
static __device__ __half g_w1bh[128 * 128];
static __device__ __half g_w2ah[128 * 128];
static __device__ __half g_w2bh[128 * 128];
static __device__ __half g_wg1h[128 * 64];
static __device__ float  g_gate[NN];
static __device__ float  g_bmax[BB];
static __device__ float  g_bsum[BB];
static __device__ int    g_part[64];
static __device__ int    g_is64e, g_is64b;

// ---------------- helpers ----------------
__device__ __forceinline__ int ldidx(const void* p, int is64, long long i) {
    if (is64) return (int)((const long long*)p)[i];
    return ((const int*)p)[i];
}

__device__ __forceinline__ float gelu(float x) {
    return 0.5f * x * (1.0f + erff(x * 0.70710678118654752440f));
}

__device__ __forceinline__ void atomicMaxF(float* a, float v) {
    int* ai = (int*)a;
    int old = *ai;
    while (__int_as_float(old) < v) {
        int assumed = old;
        old = atomicCAS(ai, assumed, __float_as_int(v));
        if (old == assumed) break;
    }
}

__device__ __forceinline__ void add8(float2 a[4], uint4 v) {
    float2 f0 = __half22float2(*(__half2*)&v.x);
    float2 f1 = __half22float2(*(__half2*)&v.y);
    float2 f2 = __half22float2(*(__half2*)&v.z);
    float2 f3 = __half22float2(*(__half2*)&v.w);
    a[0].x += f0.x; a[0].y += f0.y;
    a[1].x += f1.x; a[1].y += f1.y;
    a[2].x += f2.x; a[2].y += f2.y;
    a[3].x += f3.x; a[3].y += f3.y;
}

// ---- mma primitives ----
__device__ __forceinline__ void ldsm_x4(uint32_t& a0, uint32_t& a1, uint32_t& a2,
                                        uint32_t& a3, uint32_t addr) {
    asm volatile("ldmatrix.sync.aligned.m8n8.x4.shared.b16 {%0,%1,%2,%3},[%4];\n"
                 : "=r"(a0), "=r"(a1), "=r"(a2), "=r"(a3) : "r"(addr));
}
__device__ __forceinline__ void ldsm_x2t(uint32_t& b0, uint32_t& b1, uint32_t addr) {
    asm volatile("ldmatrix.sync.aligned.m8n8.x2.trans.shared.b16 {%0,%1},[%2];\n"
                 : "=r"(b0), "=r"(b1) : "r"(addr));
}
__device__ __forceinline__ void mma16816(float* c, uint32_t a0, uint32_t a1, uint32_t a2,
                                         uint32_t a3, uint32_t b0, uint32_t b1) {
    asm volatile(
        "mma.sync.aligned.m16n8k16.row.col.f32.f16.f16.f32 "
        "{%0,%1,%2,%3},{%4,%5,%6,%7},{%8,%9},{%0,%1,%2,%3};\n"
        : "+f"(c[0]), "+f"(c[1]), "+f"(c[2]), "+f"(c[3])
        : "r"(a0), "r"(a1), "r"(a2), "r"(a3), "r"(b0), "r"(b1));
}

// ---------------- dtype detection ----------------
__global__ void k_detect(const unsigned* ei, const unsigned* bt) {
    __shared__ unsigned s1[256], s2[256];
    int t = threadIdx.x;
    unsigned o1 = 0, o2 = 0;
    for (int i = t; i < 2048; i += 256) {
        o1 |= ei[(long long)2 * EE - 4096 + 2 * i + 1];
        o2 |= bt[NN - 4096 + 2 * i + 1];
    }
    s1[t] = o1; s2[t] = o2;
    __syncthreads();
    for (int o = 128; o; o >>= 1) {
        if (t < o) { s1[t] |= s1[t + o]; s2[t] |= s2[t + o]; }
        __syncthreads();
    }
    if (t == 0) { g_is64e = (s1[0] == 0); g_is64b = (s2[0] == 0); }
}

// ---------------- init + x->fp16 ----------------
__global__ void k_init(float* outg, const float* __restrict__ x) {
    int i = blockIdx.x * blockDim.x + threadIdx.x;
    if (i < NN) g_deg[i] = 0;
    if (i < BB) { g_bmax[i] = __int_as_float(0xff800000); g_bsum[i] = 0.f; }
    if (i < BB * 128) outg[i] = 0.f;
    if (i == 0) g_rowstart[NN] = EE;
    if (i < NN * 32) {
        float2 v = ((const float2*)x)[i];
        ((__half2*)g_x16)[i] = __float22half2_rn(v);
    }
}

// ---------------- fp16 weight conversion ----------------
__global__ void k_cvtw(const float* W1a, const float* W1b,
                       const float* W2a, const float* W2b, const float* Wg1) {
    int i = blockIdx.x * blockDim.x + threadIdx.x;
    if (i < 64 * 128) g_w1ah[i] = __float2half(W1a[i]);
    if (i < 128 * 64) g_wg1h[i] = __float2half(Wg1[i]);
    if (i < 128 * 128) {
        g_w1bh[i] = __float2half(W1b[i]);
        g_w2ah[i] = __float2half(W2a[i]);
        g_w2bh[i] = __float2half(W2b[i]);
    }
}

// ---------------- degree histogram ----------------
__global__ void k_hist(const void* ei) {
    int e = blockIdx.x * blockDim.x + threadIdx.x;
    if (e >= EE) return;
    int d = ldidx(ei, g_is64e, (long long)EE + e);
    atomicAdd(&g_deg[d], 1);
}

// ---------------- 3-phase exclusive scan ----------------
#define SCHUNK 8192
#define SNB 13

__global__ void k_scan_sum() {
    __shared__ int sh[8];
    int b = blockIdx.x, t = threadIdx.x;
    int base = b * SCHUNK, s = 0;
    for (int i = t; i < SCHUNK; i += 256) {
        int idx = base + i;
        if (idx < NN) s += g_deg[idx];
    }
    for (int o = 16; o; o >>= 1) s += __shfl_xor_sync(~0u, s, o);
    if ((t & 31) == 0) sh[t >> 5] = s;
    __syncthreads();
    if (t == 0) {
        int v = 0;
        for (int i = 0; i < 8; i++) v += sh[i];
        g_part[b] = v;
    }
}

__global__ void k_scan_part() {
    if (threadIdx.x == 0) {
        int r = 0;
        for (int i = 0; i < SNB; i++) { int v = g_part[i]; g_part[i] = r; r += v; }
    }
}

__global__ void k_scan_write() {
    __shared__ int sh[1024];
    int b = blockIdx.x, t = threadIdx.x;
    int base = b * SCHUNK + t * 8;
    int loc[8];
    int s = 0;
#pragma unroll
    for (int j = 0; j < 8; j++) {
        int idx = base + j;
        int v = (idx < NN) ? g_deg[idx] : 0;
        loc[j] = s; s += v;
    }
    sh[t] = s;
    __syncthreads();
    for (int off = 1; off < 1024; off <<= 1) {
        int v = (t >= off) ? sh[t - off] : 0;
        __syncthreads();
        sh[t] += v;
        __syncthreads();
    }
    int off0 = g_part[b] + sh[t] - s;
#pragma unroll
    for (int j = 0; j < 8; j++) {
        int idx = base + j;
        if (idx < NN) {
            int rs = off0 + loc[j];
            g_rowstart[idx] = rs;
            g_wptr[idx] = rs;
            int d = g_deg[idx] + 1;
            g_dis[idx] = rsqrtf((float)d);
            g_selfw[idx] = 1.0f / (float)d;
        }
    }
}

// ---------------- CSR build (slim records) ----------------
__global__ void k_build(const void* ei, const float* __restrict__ ea) {
    int e = blockIdx.x * blockDim.x + threadIdx.x;
    if (e >= EE) return;
    int is64 = g_is64e;
    int s = ldidx(ei, is64, e);
    int d = ldidx(ei, is64, (long long)EE + e);
    int pos = atomicAdd(&g_wptr[d], 1);
    float2 a = ((const float2*)ea)[e];
    __half2 ah = __float22half2_rn(a);
    int2 rec;
    rec.x = s;
    rec.y = *(int*)&ah;
    g_edge8[pos] = rec;
    g_esrc[pos] = s;
}

// ---------------- conv1 (64-dim, 2 rows/warp, 16 lanes x 4 cols, unroll 2) ---------
__global__ void __launch_bounds__(256) k_conv1(const float* __restrict__ x,
                                               const float* __restrict__ We1,
                                               const float* __restrict__ be1) {
    int gwarp = (blockIdx.x * blockDim.x + threadIdx.x) >> 5;
    int lane = threadIdx.x & 31;
    int row = gwarp * 2 + (lane >> 4);
    if (row >= NN) return;
    int li = lane & 15, c = li * 4;
    float4 w0 = *(const float4*)(We1 + c);
    float4 w1 = *(const float4*)(We1 + 64 + c);
    float4 bv = *(const float4*)(be1 + c);
    int beg = g_rowstart[row], end = g_rowstart[row + 1];
    float4 acc = make_float4(0.f, 0.f, 0.f, 0.f);

#define C1_BODY(ez, ew, vv)                                                 \
    {                                                                       \
        float2 f0 = __half22float2(*(__half2*)&(vv).x);                     \
        float2 f1 = __half22float2(*(__half2*)&(vv).y);                     \
        acc.x += fmaxf(f0.x + (ez) * w0.x + (ew) * w1.x + bv.x, 0.f);       \
        acc.y += fmaxf(f0.y + (ez) * w0.y + (ew) * w1.y + bv.y, 0.f);       \
        acc.z += fmaxf(f1.x + (ez) * w0.z + (ew) * w1.z + bv.z, 0.f);       \
        acc.w += fmaxf(f1.y + (ez) * w0.w + (ew) * w1.w + bv.w, 0.f);       \
    }

    int p = beg;
    for (; p + 2 <= end; p += 2) {
        int2 r0 = g_edge8[p];
        int2 r1 = g_edge8[p + 1];
        float2 e0 = __half22float2(*(__half2*)&r0.y);
        float2 e1 = __half22float2(*(__half2*)&r1.y);
        uint2 v0 = *(const uint2*)(g_x16 + (size_t)r0.x * 64 + c);
        uint2 v1 = *(const uint2*)(g_x16 + (size_t)r1.x * 64 + c);
        C1_BODY(e0.x, e0.y, v0);
        C1_BODY(e1.x, e1.y, v1);
    }
    if (p < end) {
        int2 r = g_edge8[p];
        float2 e0 = __half22float2(*(__half2*)&r.y);
        uint2 v = *(const uint2*)(g_x16 + (size_t)r.x * 64 + c);
        C1_BODY(e0.x, e0.y, v);
    }
#undef C1_BODY
    float4 xd = *(const float4*)(x + (size_t)row * 64 + c);
    uint2 o;
    *(__half2*)&o.x = __float22half2_rn(make_float2(acc.x + xd.x, acc.y + xd.y));
    *(__half2*)&o.y = __float22half2_rn(make_float2(acc.z + xd.z, acc.w + xd.w));
    *(uint2*)(g_t0h + (size_t)row * 64 + c) = o;
}

// ---------------- conv2 (128-dim, 2 rows/warp, unroll 2, slim records) ----------------
__global__ void __launch_bounds__(256) k_conv2(const __half* __restrict__ hin,
                                               __half* __restrict__ hout,
                                               const float* __restrict__ We2,
                                               const float* __restrict__ be2) {
    int gwarp = (blockIdx.x * blockDim.x + threadIdx.x) >> 5;
    int lane = threadIdx.x & 31;
    int row = gwarp * 2 + (lane >> 4);
    if (row >= NN) return;
    int li = lane & 15, c = li * 8;
    float4 w0a = *(const float4*)(We2 + c);
    float4 w0b = *(const float4*)(We2 + c + 4);
    float4 w1a = *(const float4*)(We2 + 128 + c);
    float4 w1b = *(const float4*)(We2 + 128 + c + 4);
    float4 bva = *(const float4*)(be2 + c);
    float4 bvb = *(const float4*)(be2 + c + 4);
    int beg = g_rowstart[row], end = g_rowstart[row + 1];
    float2 acc[4] = {{0.f, 0.f}, {0.f, 0.f}, {0.f, 0.f}, {0.f, 0.f}};

#define C2_BODY(ez, ew, vv)                                                   \
    {                                                                         \
        float2 f0 = __half22float2(*(__half2*)&(vv).x);                       \
        float2 f1 = __half22float2(*(__half2*)&(vv).y);                       \
        float2 f2 = __half22float2(*(__half2*)&(vv).z);                       \
        float2 f3 = __half22float2(*(__half2*)&(vv).w);                       \
        acc[0].x += fmaxf(f0.x + (ez) * w0a.x + (ew) * w1a.x + bva.x, 0.f);   \
        acc[0].y += fmaxf(f0.y + (ez) * w0a.y + (ew) * w1a.y + bva.y, 0.f);   \
        acc[1].x += fmaxf(f1.x + (ez) * w0a.z + (ew) * w1a.z + bva.z, 0.f);   \
        acc[1].y += fmaxf(f1.y + (ez) * w0a.w + (ew) * w1a.w + bva.w, 0.f);   \
        acc[2].x += fmaxf(f2.x + (ez) * w0b.x + (ew) * w1b.x + bvb.x, 0.f);   \
        acc[2].y += fmaxf(f2.y + (ez) * w0b.y + (ew) * w1b.y + bvb.y, 0.f);   \
        acc[3].x += fmaxf(f3.x + (ez) * w0b.z + (ew) * w1b.z + bvb.z, 0.f);   \
        acc[3].y += fmaxf(f3.y + (ez) * w0b.w + (ew) * w1b.w + bvb.w, 0.f);   \
    }

    int p = beg;
    for (; p + 2 <= end; p += 2) {
        int2 r0 = g_edge8[p];
        int2 r1 = g_edge8[p + 1];
        float2 e0 = __half22float2(*(__half2*)&r0.y);
        float2 e1 = __half22float2(*(__half2*)&r1.y);
        uint4 v0 = *(const uint4*)(hin + (size_t)r0.x * 128 + c);
        uint4 v1 = *(const uint4*)(hin + (size_t)r1.x * 128 + c);
        C2_BODY(e0.x, e0.y, v0);
        C2_BODY(e1.x, e1.y, v1);
    }
    if (p < end) {
        int2 r = g_edge8[p];
        float2 e0 = __half22float2(*(__half2*)&r.y);
        uint4 v = *(const uint4*)(hin + (size_t)r.x * 128 + c);
        C2_BODY(e0.x, e0.y, v);
    }
#undef C2_BODY
    uint4 hd = *(const uint4*)(hin + (size_t)row * 128 + c);
    float2 d0 = __half22float2(*(__half2*)&hd.x);
    float2 d1 = __half22float2(*(__half2*)&hd.y);
    float2 d2 = __half22float2(*(__half2*)&hd.z);
    float2 d3 = __half22float2(*(__half2*)&hd.w);
    uint4 o;
    *(__half2*)&o.x = __float22half2_rn(make_float2(d0.x + acc[0].x, d0.y + acc[0].y));
    *(__half2*)&o.y = __float22half2_rn(make_float2(d1.x + acc[1].x, d1.y + acc[1].y));
    *(__half2*)&o.z = __float22half2_rn(make_float2(d2.x + acc[2].x, d2.y + acc[2].y));
    *(__half2*)&o.w = __float22half2_rn(make_float2(d3.x + acc[3].x, d3.y + acc[3].y));
    *(uint4*)(hout + (size_t)row * 128 + c) = o;
}

// ---------------- tensor-core fused MLP(+GELU)+LayerNorm (+optional APPNP prep) ------
template <int K1, int GELU_OUT, int PREP>
__global__ void __launch_bounds__(256)
k_mlp_mma(const __half* __restrict__ in, __half* __restrict__ out,
          const __half* __restrict__ Wah, const float* __restrict__ ba,
          const __half* __restrict__ Wbh, const float* __restrict__ bb,
          const float* __restrict__ gamma, const float* __restrict__ beta,
          __half* __restrict__ u0b, __half* __restrict__ y0b) {
    extern __shared__ char smem_raw[];
    constexpr int SA_STRIDE = K1 + 8;
    __half* sWa = (__half*)smem_raw;
    __half* sWb = sWa + K1 * 136;
    __half* sA  = sWb + 128 * 136;
    __half* sU  = sA + 128 * SA_STRIDE;
    float* sBa = (float*)(sU + 128 * 136);
    float* sBb = sBa + 128;
    float* sGm = sBb + 128;
    float* sBt = sGm + 128;

    int t = threadIdx.x;
    for (int i = t; i < K1 * 16; i += 256) {
        int r = i >> 4, ch = i & 15;
        *(uint4*)(sWa + r * 136 + ch * 8) = *(const uint4*)(Wah + r * 128 + ch * 8);
    }
    for (int i = t; i < 128 * 16; i += 256) {
        int r = i >> 4, ch = i & 15;
        *(uint4*)(sWb + r * 136 + ch * 8) = *(const uint4*)(Wbh + r * 128 + ch * 8);
    }
    if (t < 128) { sBa[t] = ba[t]; sBb[t] = bb[t]; sGm[t] = gamma[t]; sBt[t] = beta[t]; }

    int nbase = blockIdx.x * 128;
    constexpr int CH = K1 / 8;
    for (int i = t; i < 128 * CH; i += 256) {
        int r = i / CH, ch = i % CH;
        int node = nbase + r;
        uint4 v = make_uint4(0, 0, 0, 0);
        if (node < NN) v = *(const uint4*)(in + (size_t)node * K1 + ch * 8);
        *(uint4*)(sA + r * SA_STRIDE + ch * 8) = v;
    }
    __syncthreads();

    int warp = t >> 5, lane = t & 31;
    int mbase = warp * 16;
    uint32_t sA_b = (uint32_t)__cvta_generic_to_shared(sA);
    uint32_t sWa_b = (uint32_t)__cvta_generic_to_shared(sWa);
    uint32_t sWb_b = (uint32_t)__cvta_generic_to_shared(sWb);

    float c[16][4];

#pragma unroll
    for (int nt = 0; nt < 16; nt++) { c[nt][0] = c[nt][1] = c[nt][2] = c[nt][3] = 0.f; }
#pragma unroll
    for (int ks = 0; ks < K1 / 16; ks++) {
        uint32_t a0, a1, a2, a3;
        uint32_t aaddr = sA_b +
            (((mbase + (lane & 15)) * SA_STRIDE + ks * 16 + ((lane >> 4) << 3)) << 1);
        ldsm_x4(a0, a1, a2, a3, aaddr);
#pragma unroll
        for (int nt = 0; nt < 16; nt++) {
            uint32_t b0, b1;
            uint32_t baddr = sWa_b + (((ks * 16 + (lane & 15)) * 136 + nt * 8) << 1);
            ldsm_x2t(b0, b1, baddr);
            mma16816(c[nt], a0, a1, a2, a3, b0, b1);
        }
    }
    {
        int r0 = lane >> 2;
#pragma unroll
        for (int nt = 0; nt < 16; nt++) {
            int col0 = nt * 8 + (lane & 3) * 2;
            float u00 = gelu(c[nt][0] + sBa[col0]);
            float u01 = gelu(c[nt][1] + sBa[col0 + 1]);
            float u10 = gelu(c[nt][2] + sBa[col0]);
            float u11 = gelu(c[nt][3] + sBa[col0 + 1]);
            *(__half2*)(sU + (mbase + r0) * 136 + col0) =
                __float22half2_rn(make_float2(u00, u01));
            *(__half2*)(sU + (mbase + r0 + 8) * 136 + col0) =
                __float22half2_rn(make_float2(u10, u11));
        }
    }
    __syncwarp();
    uint32_t sU_b = (uint32_t)__cvta_generic_to_shared(sU);

#pragma unroll
    for (int nt = 0; nt < 16; nt++) { c[nt][0] = c[nt][1] = c[nt][2] = c[nt][3] = 0.f; }
#pragma unroll
    for (int ks = 0; ks < 8; ks++) {
        uint32_t a0, a1, a2, a3;
        uint32_t aaddr = sU_b +
            (((mbase + (lane & 15)) * 136 + ks * 16 + ((lane >> 4) << 3)) << 1);
        ldsm_x4(a0, a1, a2, a3, aaddr);
#pragma unroll
        for (int nt = 0; nt < 16; nt++) {
            uint32_t b0, b1;
            uint32_t baddr = sWb_b + (((ks * 16 + (lane & 15)) * 136 + nt * 8) << 1);
            ldsm_x2t(b0, b1, baddr);
            mma16816(c[nt], a0, a1, a2, a3, b0, b1);
        }
    }

    {
        int r0 = lane >> 2;
        float s0 = 0.f, q0 = 0.f, s1 = 0.f, q1 = 0.f;
#pragma unroll
        for (int nt = 0; nt < 16; nt++) {
            int col0 = nt * 8 + (lane & 3) * 2;
            float y00 = c[nt][0] + sBb[col0];
            float y01 = c[nt][1] + sBb[col0 + 1];
            float y10 = c[nt][2] + sBb[col0];
            float y11 = c[nt][3] + sBb[col0 + 1];
            if (GELU_OUT) { y00 = gelu(y00); y01 = gelu(y01); y10 = gelu(y10); y11 = gelu(y11); }
            c[nt][0] = y00; c[nt][1] = y01; c[nt][2] = y10; c[nt][3] = y11;
            s0 += y00 + y01; q0 += y00 * y00 + y01 * y01;
            s1 += y10 + y11; q1 += y10 * y10 + y11 * y11;
        }
#pragma unroll
        for (int o = 1; o <= 2; o <<= 1) {
            s0 += __shfl_xor_sync(~0u, s0, o); q0 += __shfl_xor_sync(~0u, q0, o);
            s1 += __shfl_xor_sync(~0u, s1, o); q1 += __shfl_xor_sync(~0u, q1, o);
        }
        float mu0 = s0 * (1.f / 128.f);
        float inv0 = rsqrtf(q0 * (1.f / 128.f) - mu0 * mu0 + LN_EPS);
        float mu1 = s1 * (1.f / 128.f);
        float inv1 = rsqrtf(q1 * (1.f / 128.f) - mu1 * mu1 + LN_EPS);
        int node0 = nbase + mbase + r0;
        int node1 = node0 + 8;
        float dis0 = 0.f, dis1 = 0.f;
        if (PREP) {
            if (node0 < NN) dis0 = g_dis[node0];
            if (node1 < NN) dis1 = g_dis[node1];
        }
#pragma unroll
        for (int nt = 0; nt < 16; nt++) {
            int col0 = nt * 8 + (lane & 3) * 2;
            float gm0 = sGm[col0], gm1 = sGm[col0 + 1];
            float bt0 = sBt[col0], bt1 = sBt[col0 + 1];
            if (node0 < NN) {
                float v0 = (c[nt][0] - mu0) * inv0 * gm0 + bt0;
                float v1 = (c[nt][1] - mu0) * inv0 * gm1 + bt1;
                *(__half2*)(out + (size_t)node0 * 128 + col0) =
                    __float22half2_rn(make_float2(v0, v1));
                if (PREP) {
                    float ua = dis0 * v0, ub = dis0 * v1;
                    *(__half2*)(u0b + (size_t)node0 * 128 + col0) =
                        __float22half2_rn(make_float2(ua, ub));
                    *(__half2*)(y0b + (size_t)node0 * 128 + col0) =
                        __float22half2_rn(make_float2(0.1f * ua, 0.1f * ub));
                }
            }
            if (node1 < NN) {
                float v0 = (c[nt][2] - mu1) * inv1 * gm0 + bt0;
                float v1 = (c[nt][3] - mu1) * inv1 * gm1 + bt1;
                *(__half2*)(out + (size_t)node1 * 128 + col0) =
                    __float22half2_rn(make_float2(v0, v1));
                if (PREP) {
                    float ua = dis1 * v0, ub = dis1 * v1;
                    *(__half2*)(u0b + (size_t)node1 * 128 + col0) =
                        __float22half2_rn(make_float2(ua, ub));
                    *(__half2*)(y0b + (size_t)node1 * 128 + col0) =
                        __float22half2_rn(make_float2(0.1f * ua, 0.1f * ub));
                }
            }
        }
    }
}

// ---------------- APPNP step: 2 rows/warp, unroll 4, index software pipeline ---------
template <int FINAL>
__global__ void __launch_bounds__(256) k_appnp16(const __half* __restrict__ cur,
                                                 __half* __restrict__ nxt,
                                                 float* __restrict__ outp,
                                                 const __half* __restrict__ y0h,
                                                 const __half* __restrict__ x0h) {
    int gwarp = (blockIdx.x * blockDim.x + threadIdx.x) >> 5;
    int lane = threadIdx.x & 31;
    int row = gwarp * 2 + (lane >> 4);
    if (row >= NN) return;
    int li = lane & 15, c = li * 8;
    int beg = g_rowstart[row], end = g_rowstart[row + 1];
    float2 acc[4] = {{0.f, 0.f}, {0.f, 0.f}, {0.f, 0.f}, {0.f, 0.f}};
    int p = beg;
    int pend = beg + ((end - beg) & ~3);
    if (p < pend) {
        int s0 = g_esrc[p];
        int s1 = g_esrc[p + 1];
        int s2 = g_esrc[p + 2];
        int s3 = g_esrc[p + 3];
        for (;;) {
            uint4 v0 = *(const uint4*)(cur + (size_t)s0 * 128 + c);
            uint4 v1 = *(const uint4*)(cur + (size_t)s1 * 128 + c);
            uint4 v2 = *(const uint4*)(cur + (size_t)s2 * 128 + c);
            uint4 v3 = *(const uint4*)(cur + (size_t)s3 * 128 + c);
            p += 4;
            bool more = p < pend;
            int t0, t1, t2, t3;
            if (more) {
                t0 = g_esrc[p];
                t1 = g_esrc[p + 1];
                t2 = g_esrc[p + 2];
                t3 = g_esrc[p + 3];
            }
            add8(acc, v0);
            add8(acc, v1);
            add8(acc, v2);
            add8(acc, v3);
            if (!more) break;
            s0 = t0; s1 = t1; s2 = t2; s3 = t3;
        }
    }
    for (; p < end; p++) {
        int s = g_esrc[p];
        uint4 v = *(const uint4*)(cur + (size_t)s * 128 + c);
        add8(acc, v);
    }
    uint4 hd = *(const uint4*)(cur + (size_t)row * 128 + c);
    add8(acc, hd);  // + u_i

    if (FINAL) {
        float dis = g_dis[row];
        uint4 xv = *(const uint4*)(x0h + (size_t)row * 128 + c);
        float2 x0 = __half22float2(*(__half2*)&xv.x);
        float2 x1 = __half22float2(*(__half2*)&xv.y);
        float2 x2 = __half22float2(*(__half2*)&xv.z);
        float2 x3 = __half22float2(*(__half2*)&xv.w);
        float k = 0.9f * dis;
        float2 o0 = make_float2(k * acc[0].x + 0.1f * x0.x, k * acc[0].y + 0.1f * x0.y);
        float2 o1 = make_float2(k * acc[1].x + 0.1f * x1.x, k * acc[1].y + 0.1f * x1.y);
        float2 o2 = make_float2(k * acc[2].x + 0.1f * x2.x, k * acc[2].y + 0.1f * x2.y);
        float2 o3 = make_float2(k * acc[3].x + 0.1f * x3.x, k * acc[3].y + 0.1f * x3.y);
        float* op = outp + (size_t)row * 128 + c;
        *(float4*)op = make_float4(o0.x, o0.y, o1.x, o1.y);
        *(float4*)(op + 4) = make_float4(o2.x, o2.y, o3.x, o3.y);
        uint4 o;
        *(__half2*)&o.x = __float22half2_rn(o0);
        *(__half2*)&o.y = __float22half2_rn(o1);
        *(__half2*)&o.z = __float22half2_rn(o2);
        *(__half2*)&o.w = __float22half2_rn(o3);
        *(uint4*)(nxt + (size_t)row * 128 + c) = o;  // fp16 h copy for gate
    } else {
        float ci = 0.9f * g_selfw[row];
        uint4 yv = *(const uint4*)(y0h + (size_t)row * 128 + c);
        float2 y0 = __half22float2(*(__half2*)&yv.x);
        float2 y1 = __half22float2(*(__half2*)&yv.y);
        float2 y2 = __half22float2(*(__half2*)&yv.z);
        float2 y3 = __half22float2(*(__half2*)&yv.w);
        float2 o0 = make_float2(ci * acc[0].x + y0.x, ci * acc[0].y + y0.y);
        float2 o1 = make_float2(ci * acc[1].x + y1.x, ci * acc[1].y + y1.y);
        float2 o2 = make_float2(ci * acc[2].x + y2.x, ci * acc[2].y + y2.y);
        float2 o3 = make_float2(ci * acc[3].x + y3.x, ci * acc[3].y + y3.y);
        uint4 o;
        *(__half2*)&o.x = __float22half2_rn(o0);
        *(__half2*)&o.y = __float22half2_rn(o1);
        *(__half2*)&o.z = __float22half2_rn(o2);
        *(__half2*)&o.w = __float22half2_rn(o3);
        *(uint4*)(nxt + (size_t)row * 128 + c) = o;
    }
}

// ---------------- tensor-core gate MLP + segment max ----------------
__global__ void __launch_bounds__(256)
k_gate_mma(const __half* __restrict__ h16, const __half* __restrict__ Wg1h,
           const float* __restrict__ bg1, const float* __restrict__ Wg2,
           const float* __restrict__ bg2, const void* bt) {
    extern __shared__ char smem_raw[];
    __half* sW = (__half*)smem_raw;        // [128][72]
    __half* sA = sW + 128 * 72;            // [128][136]
    float* sB  = (float*)(sA + 128 * 136); // 64
    float* sG2 = sB + 64;                  // 64

    int t = threadIdx.x;
    for (int i = t; i < 128 * 8; i += 256) {
        int r = i >> 3, ch = i & 7;
        *(uint4*)(sW + r * 72 + ch * 8) = *(const uint4*)(Wg1h + r * 64 + ch * 8);
    }
    if (t < 64) { sB[t] = bg1[t]; sG2[t] = Wg2[t]; }

    int nbase = blockIdx.x * 128;
    for (int i = t; i < 128 * 16; i += 256) {
        int r = i >> 4, ch = i & 15;
        int node = nbase + r;
        uint4 v = make_uint4(0, 0, 0, 0);
        if (node < NN) v = *(const uint4*)(h16 + (size_t)node * 128 + ch * 8);
        *(uint4*)(sA + r * 136 + ch * 8) = v;
    }
    __syncthreads();

    int warp = t >> 5, lane = t & 31;
    int mbase = warp * 16;
    uint32_t sA_b = (uint32_t)__cvta_generic_to_shared(sA);
    uint32_t sW_b = (uint32_t)__cvta_generic_to_shared(sW);

    float c[8][4];
#pragma unroll
    for (int nt = 0; nt < 8; nt++) { c[nt][0] = c[nt][1] = c[nt][2] = c[nt][3] = 0.f; }
#pragma unroll
    for (int ks = 0; ks < 8; ks++) {
        uint32_t a0, a1, a2, a3;
        uint32_t aaddr = sA_b +
            (((mbase + (lane & 15)) * 136 + ks * 16 + ((lane >> 4) << 3)) << 1);
        ldsm_x4(a0, a1, a2, a3, aaddr);
#pragma unroll
        for (int nt = 0; nt < 8; nt++) {
            uint32_t b0, b1;
            uint32_t baddr = sW_b + (((ks * 16 + (lane & 15)) * 72 + nt * 8) << 1);
            ldsm_x2t(b0, b1, baddr);
            mma16816(c[nt], a0, a1, a2, a3, b0, b1);
        }
    }

    float p0 = 0.f, p1 = 0.f;
#pragma unroll
    for (int nt = 0; nt < 8; nt++) {
        int col0 = nt * 8 + (lane & 3) * 2;
        p0 += gelu(c[nt][0] + sB[col0]) * sG2[col0]
            + gelu(c[nt][1] + sB[col0 + 1]) * sG2[col0 + 1];
        p1 += gelu(c[nt][2] + sB[col0]) * sG2[col0]
            + gelu(c[nt][3] + sB[col0 + 1]) * sG2[col0 + 1];
    }
    p0 += __shfl_xor_sync(~0u, p0, 1); p0 += __shfl_xor_sync(~0u, p0, 2);
    p1 += __shfl_xor_sync(~0u, p1, 1); p1 += __shfl_xor_sync(~0u, p1, 2);

    if ((lane & 3) == 0) {
        int r0 = lane >> 2;
        float b2 = bg2[0];
        int is64 = g_is64b;
        int n0 = nbase + mbase + r0;
        int n1 = n0 + 8;
        if (n0 < NN) {
            float g = p0 + b2;
            g_gate[n0] = g;
            atomicMaxF(&g_bmax[ldidx(bt, is64, n0)], g);
        }
        if (n1 < NN) {
            float g = p1 + b2;
            g_gate[n1] = g;
            atomicMaxF(&g_bmax[ldidx(bt, is64, n1)], g);
        }
    }
}

// ---------------- pooling: exp + weighted sum + bsum, fused ----------------
#define GCHUNK 512
__global__ void __launch_bounds__(128) k_gagg(const __half* __restrict__ h16,
                                              float* __restrict__ outg,
                                              const void* bt) {
    int j = threadIdx.x;
    int base = blockIdx.x * GCHUNK;
    int lim = base + GCHUNK;
    if (lim > NN) lim = NN;
    int is64 = g_is64b;
    float acc = 0.f, esum = 0.f;
    int curb = -1;
    float bmax = 0.f;
    for (int n = base; n < lim; n++) {
        int b = ldidx(bt, is64, n);
        if (b != curb) {
            if (curb >= 0) {
                atomicAdd(&outg[curb * 128 + j], acc);
                if (j == 0) atomicAdd(&g_bsum[curb], esum);
            }
            curb = b;
            acc = 0.f; esum = 0.f;
            bmax = g_bmax[b];
        }
        float e = expf(g_gate[n] - bmax);
        acc += e * __half2float(h16[(size_t)n * 128 + j]);
        if (j == 0) esum += e;
    }
    if (curb >= 0) {
        atomicAdd(&outg[curb * 128 + j], acc);
        if (j == 0) atomicAdd(&g_bsum[curb], esum);
    }
}

__global__ void k_gdiv(float* __restrict__ outg) {
    int i = blockIdx.x * blockDim.x + threadIdx.x;
    if (i >= BB * 128) return;
    float s = g_bsum[i >> 7];
    if (s > 0.f) outg[i] /= s;
}

// ---------------- launch ----------------
extern "C" void kernel_launch(void* const* d_in, const int* in_sizes, int n_in,
                              void* d_out, int out_size) {
    const float* x = (const float*)d_in[0];
    const void* ei = d_in[1];
    const void* bt = d_in[2];
    const float* ea = (const float*)d_in[3];
    const float* We1 = (const float*)d_in[4];  const float* be1 = (const float*)d_in[5];
    const float* W1a = (const float*)d_in[6];  const float* b1a = (const float*)d_in[7];
    const float* W1b = (const float*)d_in[8];  const float* b1b = (const float*)d_in[9];
    const float* g1  = (const float*)d_in[10]; const float* bn1 = (const float*)d_in[11];
    const float* We2 = (const float*)d_in[12]; const float* be2 = (const float*)d_in[13];
    const float* W2a = (const float*)d_in[14]; const float* b2a = (const float*)d_in[15];
    const float* W2b = (const float*)d_in[16]; const float* b2b = (const float*)d_in[17];
    const float* g2  = (const float*)d_in[18]; const float* bn2 = (const float*)d_in[19];
    const float* Wg1 = (const float*)d_in[20]; const float* bg1 = (const float*)d_in[21];
    const float* Wg2 = (const float*)d_in[22]; const float* bg2 = (const float*)d_in[23];

    float* outh = (float*)d_out;
    float* outg = outh + (size_t)NN * 128;

    __half *pT0h, *pHBh, *pA16, *pB16, *pX0h, *pW1ah, *pW1bh, *pW2ah, *pW2bh, *pWg1h;
    cudaGetSymbolAddress((void**)&pT0h, g_t0h);
    cudaGetSymbolAddress((void**)&pHBh, g_hBh);
    cudaGetSymbolAddress((void**)&pA16, g_h16A);
    cudaGetSymbolAddress((void**)&pB16, g_h16B);
    cudaGetSymbolAddress((void**)&pX0h, g_x0h);
    cudaGetSymbolAddress((void**)&pW1ah, g_w1ah);
    cudaGetSymbolAddress((void**)&pW1bh, g_w1bh);
    cudaGetSymbolAddress((void**)&pW2ah, g_w2ah);
    cudaGetSymbolAddress((void**)&pW2bh, g_w2bh);
    cudaGetSymbolAddress((void**)&pWg1h, g_wg1h);

    size_t sz1 = (size_t)(64 * 136 + 128 * 136 + 128 * 72 + 128 * 136) * 2 + 4 * 128 * 4;
    size_t sz2 = (size_t)(128 * 136 + 128 * 136 + 128 * 136 + 128 * 136) * 2 + 4 * 128 * 4;
    size_t szg = (size_t)(128 * 72 + 128 * 136) * 2 + 2 * 64 * 4;
    cudaFuncSetAttribute(k_mlp_mma<64, 1, 0>, cudaFuncAttributeMaxDynamicSharedMemorySize, (int)sz1);
    cudaFuncSetAttribute(k_mlp_mma<128, 0, 1>, cudaFuncAttributeMaxDynamicSharedMemorySize, (int)sz2);
    cudaFuncSetAttribute(k_gate_mma, cudaFuncAttributeMaxDynamicSharedMemorySize, (int)szg);

    k_detect<<<1, 256>>>((const unsigned*)ei, (const unsigned*)bt);
    k_init<<<(NN * 32 + 255) / 256, 256>>>(outg, x);
    k_cvtw<<<64, 256>>>(W1a, W1b, W2a, W2b, Wg1);
    k_hist<<<(EE + 255) / 256, 256>>>(ei);
    k_scan_sum<<<SNB, 256>>>();
    k_scan_part<<<1, 32>>>();
    k_scan_write<<<SNB, 1024>>>();
    k_build<<<(EE + 255) / 256, 256>>>(ei, ea);

    int ntile = (NN + 127) / 128;
    int pair_blocks = ((NN + 1) / 2 * 32 + 255) / 256;
    k_conv1<<<pair_blocks, 256>>>(x, We1, be1);
    k_mlp_mma<64, 1, 0><<<ntile, 256, sz1>>>(pT0h, pA16, pW1ah, b1a, pW1bh, b1b, g1, bn1,
                                             nullptr, nullptr);
    k_conv2<<<pair_blocks, 256>>>(pA16, pHBh, We2, be2);
    // mlp2: in=pHBh, out=x0h, fused prep: u0 -> pA16, y0 -> pB16
    k_mlp_mma<128, 0, 1><<<ntile, 256, sz2>>>(pHBh, pX0h, pW2ah, b2a, pW2bh, b2b, g2, bn2,
                                              pA16, pB16);

    // APPNP: u ping-pong pA16 <-> pHBh, y0 in pB16
    const __half* cur = pA16;
    for (int it = 0; it < 15; it++) {
        __half* nxt = (it & 1) ? pA16 : pHBh;
        k_appnp16<0><<<pair_blocks, 256>>>(cur, nxt, nullptr, pB16, pX0h);
        cur = nxt;
    }
    // final (it15): cur=pHBh; fp32 outh + fp16 h copy into pA16
    k_appnp16<1><<<pair_blocks, 256>>>(cur, pA16, outh, pB16, pX0h);

    k_gate_mma<<<ntile, 256, szg>>>(pA16, pWg1h, bg1, Wg2, bg2, bt);
    k_gagg<<<(NN + GCHUNK - 1) / GCHUNK, 128>>>(pA16, outg, bt);
    k_gdiv<<<(BB * 128 + 255) / 256, 256>>>(outg);
}

// round 16
// speedup vs baseline: 1.1894x; 1.1894x over previous
#include <cuda_runtime.h>
#include <cuda_fp16.h>
#include <math.h>
#include <stdint.h>

#define NN 100000
#define EE 1600000
#define BB 64
#define LN_EPS 1e-5f

// ---------------- scratch ----------------
static __device__ int    g_deg[NN];
static __device__ int    g_rowstart[NN + 1];
static __device__ int    g_wptr[NN];
static __device__ float  g_dis[NN];
static __device__ float  g_selfw[NN];
static __device__ int2   g_edge8[EE];         // {src, half2(ea0,ea1)} (convs)
static __device__ int    g_esrc[EE];          // src only (APPNP)
static __device__ __half g_x16[NN * 64];
static __device__ __half g_t0h[NN * 64];
static __device__ __half g_hBh[NN * 128];     // conv2 out -> mlp2 in -> APPNP pong
static __device__ __half g_h16A[NN * 128];    // u ping
static __device__ __half g_h16B[NN * 128];    // y0
static __device__ __half g_x0h[NN * 128];     // mlp2 out (h0 = x0), kept intact
static __device__ __half g_w1ah[64 * 128];
static __device__ __half g_w1bh[128 * 128];
static __device__ __half g_w2ah[128 * 128];
static __device__ __half g_w2bh[128 * 128];
static __device__ __half g_wg1h[128 * 64];
static __device__ float  g_gate[NN];
static __device__ float  g_bmax[BB];
static __device__ float  g_bsum[BB];
static __device__ int    g_part[64];
static __device__ int    g_is64e, g_is64b;

// ---------------- helpers ----------------
__device__ __forceinline__ int ldidx(const void* p, int is64, long long i) {
    if (is64) return (int)((const long long*)p)[i];
    return ((const int*)p)[i];
}

__device__ __forceinline__ float gelu(float x) {
    return 0.5f * x * (1.0f + erff(x * 0.70710678118654752440f));
}

__device__ __forceinline__ void atomicMaxF(float* a, float v) {
    int* ai = (int*)a;
    int old = *ai;
    while (__int_as_float(old) < v) {
        int assumed = old;
        old = atomicCAS(ai, assumed, __float_as_int(v));
        if (old == assumed) break;
    }
}

__device__ __forceinline__ void add8(float2 a[4], uint4 v) {
    float2 f0 = __half22float2(*(__half2*)&v.x);
    float2 f1 = __half22float2(*(__half2*)&v.y);
    float2 f2 = __half22float2(*(__half2*)&v.z);
    float2 f3 = __half22float2(*(__half2*)&v.w);
    a[0].x += f0.x; a[0].y += f0.y;
    a[1].x += f1.x; a[1].y += f1.y;
    a[2].x += f2.x; a[2].y += f2.y;
    a[3].x += f3.x; a[3].y += f3.y;
}

// ---- mma primitives ----
__device__ __forceinline__ void ldsm_x4(uint32_t& a0, uint32_t& a1, uint32_t& a2,
                                        uint32_t& a3, uint32_t addr) {
    asm volatile("ldmatrix.sync.aligned.m8n8.x4.shared.b16 {%0,%1,%2,%3},[%4];\n"
                 : "=r"(a0), "=r"(a1), "=r"(a2), "=r"(a3) : "r"(addr));
}
__device__ __forceinline__ void ldsm_x2t(uint32_t& b0, uint32_t& b1, uint32_t addr) {
    asm volatile("ldmatrix.sync.aligned.m8n8.x2.trans.shared.b16 {%0,%1},[%2];\n"
                 : "=r"(b0), "=r"(b1) : "r"(addr));
}
__device__ __forceinline__ void mma16816(float* c, uint32_t a0, uint32_t a1, uint32_t a2,
                                         uint32_t a3, uint32_t b0, uint32_t b1) {
    asm volatile(
        "mma.sync.aligned.m16n8k16.row.col.f32.f16.f16.f32 "
        "{%0,%1,%2,%3},{%4,%5,%6,%7},{%8,%9},{%0,%1,%2,%3};\n"
        : "+f"(c[0]), "+f"(c[1]), "+f"(c[2]), "+f"(c[3])
        : "r"(a0), "r"(a1), "r"(a2), "r"(a3), "r"(b0), "r"(b1));
}

// ---------------- dtype detection ----------------
__global__ void k_detect(const unsigned* ei, const unsigned* bt) {
    __shared__ unsigned s1[256], s2[256];
    int t = threadIdx.x;
    unsigned o1 = 0, o2 = 0;
    for (int i = t; i < 2048; i += 256) {
        o1 |= ei[(long long)2 * EE - 4096 + 2 * i + 1];
        o2 |= bt[NN - 4096 + 2 * i + 1];
    }
    s1[t] = o1; s2[t] = o2;
    __syncthreads();
    for (int o = 128; o; o >>= 1) {
        if (t < o) { s1[t] |= s1[t + o]; s2[t] |= s2[t + o]; }
        __syncthreads();
    }
    if (t == 0) { g_is64e = (s1[0] == 0); g_is64b = (s2[0] == 0); }
}

// ---------------- init + x->fp16 ----------------
__global__ void k_init(float* outg, const float* __restrict__ x) {
    int i = blockIdx.x * blockDim.x + threadIdx.x;
    if (i < NN) g_deg[i] = 0;
    if (i < BB) { g_bmax[i] = __int_as_float(0xff800000); g_bsum[i] = 0.f; }
    if (i < BB * 128) outg[i] = 0.f;
    if (i == 0) g_rowstart[NN] = EE;
    if (i < NN * 32) {
        float2 v = ((const float2*)x)[i];
        ((__half2*)g_x16)[i] = __float22half2_rn(v);
    }
}

// ---------------- fp16 weight conversion ----------------
__global__ void k_cvtw(const float* W1a, const float* W1b,
                       const float* W2a, const float* W2b, const float* Wg1) {
    int i = blockIdx.x * blockDim.x + threadIdx.x;
    if (i < 64 * 128) g_w1ah[i] = __float2half(W1a[i]);
    if (i < 128 * 64) g_wg1h[i] = __float2half(Wg1[i]);
    if (i < 128 * 128) {
        g_w1bh[i] = __float2half(W1b[i]);
        g_w2ah[i] = __float2half(W2a[i]);
        g_w2bh[i] = __float2half(W2b[i]);
    }
}

// ---------------- degree histogram ----------------
__global__ void k_hist(const void* ei) {
    int e = blockIdx.x * blockDim.x + threadIdx.x;
    if (e >= EE) return;
    int d = ldidx(ei, g_is64e, (long long)EE + e);
    atomicAdd(&g_deg[d], 1);
}

// ---------------- 3-phase exclusive scan ----------------
#define SCHUNK 8192
#define SNB 13

__global__ void k_scan_sum() {
    __shared__ int sh[8];
    int b = blockIdx.x, t = threadIdx.x;
    int base = b * SCHUNK, s = 0;
    for (int i = t; i < SCHUNK; i += 256) {
        int idx = base + i;
        if (idx < NN) s += g_deg[idx];
    }
    for (int o = 16; o; o >>= 1) s += __shfl_xor_sync(~0u, s, o);
    if ((t & 31) == 0) sh[t >> 5] = s;
    __syncthreads();
    if (t == 0) {
        int v = 0;
        for (int i = 0; i < 8; i++) v += sh[i];
        g_part[b] = v;
    }
}

__global__ void k_scan_part() {
    if (threadIdx.x == 0) {
        int r = 0;
        for (int i = 0; i < SNB; i++) { int v = g_part[i]; g_part[i] = r; r += v; }
    }
}

__global__ void k_scan_write() {
    __shared__ int sh[1024];
    int b = blockIdx.x, t = threadIdx.x;
    int base = b * SCHUNK + t * 8;
    int loc[8];
    int s = 0;
#pragma unroll
    for (int j = 0; j < 8; j++) {
        int idx = base + j;
        int v = (idx < NN) ? g_deg[idx] : 0;
        loc[j] = s; s += v;
    }
    sh[t] = s;
    __syncthreads();
    for (int off = 1; off < 1024; off <<= 1) {
        int v = (t >= off) ? sh[t - off] : 0;
        __syncthreads();
        sh[t] += v;
        __syncthreads();
    }
    int off0 = g_part[b] + sh[t] - s;
#pragma unroll
    for (int j = 0; j < 8; j++) {
        int idx = base + j;
        if (idx < NN) {
            int rs = off0 + loc[j];
            g_rowstart[idx] = rs;
            g_wptr[idx] = rs;
            int d = g_deg[idx] + 1;
            g_dis[idx] = rsqrtf((float)d);
            g_selfw[idx] = 1.0f / (float)d;
        }
    }
}

// ---------------- CSR build (slim records) ----------------
__global__ void k_build(const void* ei, const float* __restrict__ ea) {
    int e = blockIdx.x * blockDim.x + threadIdx.x;
    if (e >= EE) return;
    int is64 = g_is64e;
    int s = ldidx(ei, is64, e);
    int d = ldidx(ei, is64, (long long)EE + e);
    int pos = atomicAdd(&g_wptr[d], 1);
    float2 a = ((const float2*)ea)[e];
    __half2 ah = __float22half2_rn(a);
    int2 rec;
    rec.x = s;
    rec.y = *(int*)&ah;
    g_edge8[pos] = rec;
    g_esrc[pos] = s;
}

// ---------------- conv1 (64-dim, warp per dst, unroll 2, slim records) ----------------
__global__ void __launch_bounds__(256) k_conv1(const float* __restrict__ x,
                                               const float* __restrict__ We1,
                                               const float* __restrict__ be1) {
    int gt = blockIdx.x * blockDim.x + threadIdx.x;
    int row = gt >> 5;
    if (row >= NN) return;
    int lane = gt & 31, c = 2 * lane;
    float w0x = We1[c], w0y = We1[c + 1];
    float w1x = We1[64 + c], w1y = We1[64 + c + 1];
    float bx = be1[c], by = be1[c + 1];
    int beg = g_rowstart[row], end = g_rowstart[row + 1];
    float ax = 0.f, ay = 0.f;
    int p = beg;
    for (; p + 2 <= end; p += 2) {
        int2 r0 = g_edge8[p];
        int2 r1 = g_edge8[p + 1];
        float2 e0 = __half22float2(*(__half2*)&r0.y);
        float2 e1 = __half22float2(*(__half2*)&r1.y);
        float2 xv0 = __half22float2(*(const __half2*)(g_x16 + (size_t)r0.x * 64 + c));
        float2 xv1 = __half22float2(*(const __half2*)(g_x16 + (size_t)r1.x * 64 + c));
        ax += fmaxf(xv0.x + e0.x * w0x + e0.y * w1x + bx, 0.f);
        ay += fmaxf(xv0.y + e0.x * w0y + e0.y * w1y + by, 0.f);
        ax += fmaxf(xv1.x + e1.x * w0x + e1.y * w1x + bx, 0.f);
        ay += fmaxf(xv1.y + e1.x * w0y + e1.y * w1y + by, 0.f);
    }
    if (p < end) {
        int2 r = g_edge8[p];
        float2 e0 = __half22float2(*(__half2*)&r.y);
        float2 xv = __half22float2(*(const __half2*)(g_x16 + (size_t)r.x * 64 + c));
        ax += fmaxf(xv.x + e0.x * w0x + e0.y * w1x + bx, 0.f);
        ay += fmaxf(xv.y + e0.x * w0y + e0.y * w1y + by, 0.f);
    }
    float2 xd = *(const float2*)(x + (size_t)row * 64 + c);
    *(__half2*)(g_t0h + (size_t)row * 64 + c) =
        __float22half2_rn(make_float2(ax + xd.x, ay + xd.y));
}

// ---------------- conv2 (128-dim, 2 rows/warp, unroll 2, slim records) ----------------
__global__ void __launch_bounds__(256) k_conv2(const __half* __restrict__ hin,
                                               __half* __restrict__ hout,
                                               const float* __restrict__ We2,
                                               const float* __restrict__ be2) {
    int gwarp = (blockIdx.x * blockDim.x + threadIdx.x) >> 5;
    int lane = threadIdx.x & 31;
    int row = gwarp * 2 + (lane >> 4);
    if (row >= NN) return;
    int li = lane & 15, c = li * 8;
    float4 w0a = *(const float4*)(We2 + c);
    float4 w0b = *(const float4*)(We2 + c + 4);
    float4 w1a = *(const float4*)(We2 + 128 + c);
    float4 w1b = *(const float4*)(We2 + 128 + c + 4);
    float4 bva = *(const float4*)(be2 + c);
    float4 bvb = *(const float4*)(be2 + c + 4);
    int beg = g_rowstart[row], end = g_rowstart[row + 1];
    float2 acc[4] = {{0.f, 0.f}, {0.f, 0.f}, {0.f, 0.f}, {0.f, 0.f}};

#define C2_BODY(ez, ew, vv)                                                   \
    {                                                                         \
        float2 f0 = __half22float2(*(__half2*)&(vv).x);                       \
        float2 f1 = __half22float2(*(__half2*)&(vv).y);                       \
        float2 f2 = __half22float2(*(__half2*)&(vv).z);                       \
        float2 f3 = __half22float2(*(__half2*)&(vv).w);                       \
        acc[0].x += fmaxf(f0.x + (ez) * w0a.x + (ew) * w1a.x + bva.x, 0.f);   \
        acc[0].y += fmaxf(f0.y + (ez) * w0a.y + (ew) * w1a.y + bva.y, 0.f);   \
        acc[1].x += fmaxf(f1.x + (ez) * w0a.z + (ew) * w1a.z + bva.z, 0.f);   \
        acc[1].y += fmaxf(f1.y + (ez) * w0a.w + (ew) * w1a.w + bva.w, 0.f);   \
        acc[2].x += fmaxf(f2.x + (ez) * w0b.x + (ew) * w1b.x + bvb.x, 0.f);   \
        acc[2].y += fmaxf(f2.y + (ez) * w0b.y + (ew) * w1b.y + bvb.y, 0.f);   \
        acc[3].x += fmaxf(f3.x + (ez) * w0b.z + (ew) * w1b.z + bvb.z, 0.f);   \
        acc[3].y += fmaxf(f3.y + (ez) * w0b.w + (ew) * w1b.w + bvb.w, 0.f);   \
    }

    int p = beg;
    for (; p + 2 <= end; p += 2) {
        int2 r0 = g_edge8[p];
        int2 r1 = g_edge8[p + 1];
        float2 e0 = __half22float2(*(__half2*)&r0.y);
        float2 e1 = __half22float2(*(__half2*)&r1.y);
        uint4 v0 = *(const uint4*)(hin + (size_t)r0.x * 128 + c);
        uint4 v1 = *(const uint4*)(hin + (size_t)r1.x * 128 + c);
        C2_BODY(e0.x, e0.y, v0);
        C2_BODY(e1.x, e1.y, v1);
    }
    if (p < end) {
        int2 r = g_edge8[p];
        float2 e0 = __half22float2(*(__half2*)&r.y);
        uint4 v = *(const uint4*)(hin + (size_t)r.x * 128 + c);
        C2_BODY(e0.x, e0.y, v);
    }
#undef C2_BODY
    uint4 hd = *(const uint4*)(hin + (size_t)row * 128 + c);
    float2 d0 = __half22float2(*(__half2*)&hd.x);
    float2 d1 = __half22float2(*(__half2*)&hd.y);
    float2 d2 = __half22float2(*(__half2*)&hd.z);
    float2 d3 = __half22float2(*(__half2*)&hd.w);
    uint4 o;
    *(__half2*)&o.x = __float22half2_rn(make_float2(d0.x + acc[0].x, d0.y + acc[0].y));
    *(__half2*)&o.y = __float22half2_rn(make_float2(d1.x + acc[1].x, d1.y + acc[1].y));
    *(__half2*)&o.z = __float22half2_rn(make_float2(d2.x + acc[2].x, d2.y + acc[2].y));
    *(__half2*)&o.w = __float22half2_rn(make_float2(d3.x + acc[3].x, d3.y + acc[3].y));
    *(uint4*)(hout + (size_t)row * 128 + c) = o;
}

// ---------------- tensor-core fused MLP(+GELU)+LayerNorm (+optional APPNP prep) ------
template <int K1, int GELU_OUT, int PREP>
__global__ void __launch_bounds__(256)
k_mlp_mma(const __half* __restrict__ in, __half* __restrict__ out,
          const __half* __restrict__ Wah, const float* __restrict__ ba,
          const __half* __restrict__ Wbh, const float* __restrict__ bb,
          const float* __restrict__ gamma, const float* __restrict__ beta,
          __half* __restrict__ u0b, __half* __restrict__ y0b) {
    extern __shared__ char smem_raw[];
    constexpr int SA_STRIDE = K1 + 8;
    __half* sWa = (__half*)smem_raw;
    __half* sWb = sWa + K1 * 136;
    __half* sA  = sWb + 128 * 136;
    __half* sU  = sA + 128 * SA_STRIDE;
    float* sBa = (float*)(sU + 128 * 136);
    float* sBb = sBa + 128;
    float* sGm = sBb + 128;
    float* sBt = sGm + 128;

    int t = threadIdx.x;
    for (int i = t; i < K1 * 16; i += 256) {
        int r = i >> 4, ch = i & 15;
        *(uint4*)(sWa + r * 136 + ch * 8) = *(const uint4*)(Wah + r * 128 + ch * 8);
    }
    for (int i = t; i < 128 * 16; i += 256) {
        int r = i >> 4, ch = i & 15;
        *(uint4*)(sWb + r * 136 + ch * 8) = *(const uint4*)(Wbh + r * 128 + ch * 8);
    }
    if (t < 128) { sBa[t] = ba[t]; sBb[t] = bb[t]; sGm[t] = gamma[t]; sBt[t] = beta[t]; }

    int nbase = blockIdx.x * 128;
    constexpr int CH = K1 / 8;
    for (int i = t; i < 128 * CH; i += 256) {
        int r = i / CH, ch = i % CH;
        int node = nbase + r;
        uint4 v = make_uint4(0, 0, 0, 0);
        if (node < NN) v = *(const uint4*)(in + (size_t)node * K1 + ch * 8);
        *(uint4*)(sA + r * SA_STRIDE + ch * 8) = v;
    }
    __syncthreads();

    int warp = t >> 5, lane = t & 31;
    int mbase = warp * 16;
    uint32_t sA_b = (uint32_t)__cvta_generic_to_shared(sA);
    uint32_t sWa_b = (uint32_t)__cvta_generic_to_shared(sWa);
    uint32_t sWb_b = (uint32_t)__cvta_generic_to_shared(sWb);

    float c[16][4];

#pragma unroll
    for (int nt = 0; nt < 16; nt++) { c[nt][0] = c[nt][1] = c[nt][2] = c[nt][3] = 0.f; }
#pragma unroll
    for (int ks = 0; ks < K1 / 16; ks++) {
        uint32_t a0, a1, a2, a3;
        uint32_t aaddr = sA_b +
            (((mbase + (lane & 15)) * SA_STRIDE + ks * 16 + ((lane >> 4) << 3)) << 1);
        ldsm_x4(a0, a1, a2, a3, aaddr);
#pragma unroll
        for (int nt = 0; nt < 16; nt++) {
            uint32_t b0, b1;
            uint32_t baddr = sWa_b + (((ks * 16 + (lane & 15)) * 136 + nt * 8) << 1);
            ldsm_x2t(b0, b1, baddr);
            mma16816(c[nt], a0, a1, a2, a3, b0, b1);
        }
    }
    {
        int r0 = lane >> 2;
#pragma unroll
        for (int nt = 0; nt < 16; nt++) {
            int col0 = nt * 8 + (lane & 3) * 2;
            float u00 = gelu(c[nt][0] + sBa[col0]);
            float u01 = gelu(c[nt][1] + sBa[col0 + 1]);
            float u10 = gelu(c[nt][2] + sBa[col0]);
            float u11 = gelu(c[nt][3] + sBa[col0 + 1]);
            *(__half2*)(sU + (mbase + r0) * 136 + col0) =
                __float22half2_rn(make_float2(u00, u01));
            *(__half2*)(sU + (mbase + r0 + 8) * 136 + col0) =
                __float22half2_rn(make_float2(u10, u11));
        }
    }
    __syncwarp();
    uint32_t sU_b = (uint32_t)__cvta_generic_to_shared(sU);

#pragma unroll
    for (int nt = 0; nt < 16; nt++) { c[nt][0] = c[nt][1] = c[nt][2] = c[nt][3] = 0.f; }
#pragma unroll
    for (int ks = 0; ks < 8; ks++) {
        uint32_t a0, a1, a2, a3;
        uint32_t aaddr = sU_b +
            (((mbase + (lane & 15)) * 136 + ks * 16 + ((lane >> 4) << 3)) << 1);
        ldsm_x4(a0, a1, a2, a3, aaddr);
#pragma unroll
        for (int nt = 0; nt < 16; nt++) {
            uint32_t b0, b1;
            uint32_t baddr = sWb_b + (((ks * 16 + (lane & 15)) * 136 + nt * 8) << 1);
            ldsm_x2t(b0, b1, baddr);
            mma16816(c[nt], a0, a1, a2, a3, b0, b1);
        }
    }

    {
        int r0 = lane >> 2;
        float s0 = 0.f, q0 = 0.f, s1 = 0.f, q1 = 0.f;
#pragma unroll
        for (int nt = 0; nt < 16; nt++) {
            int col0 = nt * 8 + (lane & 3) * 2;
            float y00 = c[nt][0] + sBb[col0];
            float y01 = c[nt][1] + sBb[col0 + 1];
            float y10 = c[nt][2] + sBb[col0];
            float y11 = c[nt][3] + sBb[col0 + 1];
            if (GELU_OUT) { y00 = gelu(y00); y01 = gelu(y01); y10 = gelu(y10); y11 = gelu(y11); }
            c[nt][0] = y00; c[nt][1] = y01; c[nt][2] = y10; c[nt][3] = y11;
            s0 += y00 + y01; q0 += y00 * y00 + y01 * y01;
            s1 += y10 + y11; q1 += y10 * y10 + y11 * y11;
        }
#pragma unroll
        for (int o = 1; o <= 2; o <<= 1) {
            s0 += __shfl_xor_sync(~0u, s0, o); q0 += __shfl_xor_sync(~0u, q0, o);
            s1 += __shfl_xor_sync(~0u, s1, o); q1 += __shfl_xor_sync(~0u, q1, o);
        }
        float mu0 = s0 * (1.f / 128.f);
        float inv0 = rsqrtf(q0 * (1.f / 128.f) - mu0 * mu0 + LN_EPS);
        float mu1 = s1 * (1.f / 128.f);
        float inv1 = rsqrtf(q1 * (1.f / 128.f) - mu1 * mu1 + LN_EPS);
        int node0 = nbase + mbase + r0;
        int node1 = node0 + 8;
        float dis0 = 0.f, dis1 = 0.f;
        if (PREP) {
            if (node0 < NN) dis0 = g_dis[node0];
            if (node1 < NN) dis1 = g_dis[node1];
        }
#pragma unroll
        for (int nt = 0; nt < 16; nt++) {
            int col0 = nt * 8 + (lane & 3) * 2;
            float gm0 = sGm[col0], gm1 = sGm[col0 + 1];
            float bt0 = sBt[col0], bt1 = sBt[col0 + 1];
            if (node0 < NN) {
                float v0 = (c[nt][0] - mu0) * inv0 * gm0 + bt0;
                float v1 = (c[nt][1] - mu0) * inv0 * gm1 + bt1;
                *(__half2*)(out + (size_t)node0 * 128 + col0) =
                    __float22half2_rn(make_float2(v0, v1));
                if (PREP) {
                    float ua = dis0 * v0, ub = dis0 * v1;
                    *(__half2*)(u0b + (size_t)node0 * 128 + col0) =
                        __float22half2_rn(make_float2(ua, ub));
                    *(__half2*)(y0b + (size_t)node0 * 128 + col0) =
                        __float22half2_rn(make_float2(0.1f * ua, 0.1f * ub));
                }
            }
            if (node1 < NN) {
                float v0 = (c[nt][2] - mu1) * inv1 * gm0 + bt0;
                float v1 = (c[nt][3] - mu1) * inv1 * gm1 + bt1;
                *(__half2*)(out + (size_t)node1 * 128 + col0) =
                    __float22half2_rn(make_float2(v0, v1));
                if (PREP) {
                    float ua = dis1 * v0, ub = dis1 * v1;
                    *(__half2*)(u0b + (size_t)node1 * 128 + col0) =
                        __float22half2_rn(make_float2(ua, ub));
                    *(__half2*)(y0b + (size_t)node1 * 128 + col0) =
                        __float22half2_rn(make_float2(0.1f * ua, 0.1f * ub));
                }
            }
        }
    }
}

// ---------------- APPNP step on u-state (R9/R11 config: 2 rows/warp, unroll 4) -------
template <int FINAL>
__global__ void __launch_bounds__(256) k_appnp16(const __half* __restrict__ cur,
                                                 __half* __restrict__ nxt,
                                                 float* __restrict__ outp,
                                                 const __half* __restrict__ y0h,
                                                 const __half* __restrict__ x0h) {
    int gwarp = (blockIdx.x * blockDim.x + threadIdx.x) >> 5;
    int lane = threadIdx.x & 31;
    int row = gwarp * 2 + (lane >> 4);
    if (row >= NN) return;
    int li = lane & 15, c = li * 8;
    int beg = g_rowstart[row], end = g_rowstart[row + 1];
    float2 acc[4] = {{0.f, 0.f}, {0.f, 0.f}, {0.f, 0.f}, {0.f, 0.f}};
    int p = beg;
    for (; p + 4 <= end; p += 4) {
        int s0 = g_esrc[p];
        int s1 = g_esrc[p + 1];
        int s2 = g_esrc[p + 2];
        int s3 = g_esrc[p + 3];
        uint4 v0 = *(const uint4*)(cur + (size_t)s0 * 128 + c);
        uint4 v1 = *(const uint4*)(cur + (size_t)s1 * 128 + c);
        uint4 v2 = *(const uint4*)(cur + (size_t)s2 * 128 + c);
        uint4 v3 = *(const uint4*)(cur + (size_t)s3 * 128 + c);
        add8(acc, v0);
        add8(acc, v1);
        add8(acc, v2);
        add8(acc, v3);
    }
    for (; p < end; p++) {
        int s = g_esrc[p];
        uint4 v = *(const uint4*)(cur + (size_t)s * 128 + c);
        add8(acc, v);
    }
    uint4 hd = *(const uint4*)(cur + (size_t)row * 128 + c);
    add8(acc, hd);  // + u_i

    if (FINAL) {
        float dis = g_dis[row];
        uint4 xv = *(const uint4*)(x0h + (size_t)row * 128 + c);
        float2 x0 = __half22float2(*(__half2*)&xv.x);
        float2 x1 = __half22float2(*(__half2*)&xv.y);
        float2 x2 = __half22float2(*(__half2*)&xv.z);
        float2 x3 = __half22float2(*(__half2*)&xv.w);
        float k = 0.9f * dis;
        float2 o0 = make_float2(k * acc[0].x + 0.1f * x0.x, k * acc[0].y + 0.1f * x0.y);
        float2 o1 = make_float2(k * acc[1].x + 0.1f * x1.x, k * acc[1].y + 0.1f * x1.y);
        float2 o2 = make_float2(k * acc[2].x + 0.1f * x2.x, k * acc[2].y + 0.1f * x2.y);
        float2 o3 = make_float2(k * acc[3].x + 0.1f * x3.x, k * acc[3].y + 0.1f * x3.y);
        float* op = outp + (size_t)row * 128 + c;
        *(float4*)op = make_float4(o0.x, o0.y, o1.x, o1.y);
        *(float4*)(op + 4) = make_float4(o2.x, o2.y, o3.x, o3.y);
        uint4 o;
        *(__half2*)&o.x = __float22half2_rn(o0);
        *(__half2*)&o.y = __float22half2_rn(o1);
        *(__half2*)&o.z = __float22half2_rn(o2);
        *(__half2*)&o.w = __float22half2_rn(o3);
        *(uint4*)(nxt + (size_t)row * 128 + c) = o;  // fp16 h copy for gate
    } else {
        float ci = 0.9f * g_selfw[row];
        uint4 yv = *(const uint4*)(y0h + (size_t)row * 128 + c);
        float2 y0 = __half22float2(*(__half2*)&yv.x);
        float2 y1 = __half22float2(*(__half2*)&yv.y);
        float2 y2 = __half22float2(*(__half2*)&yv.z);
        float2 y3 = __half22float2(*(__half2*)&yv.w);
        float2 o0 = make_float2(ci * acc[0].x + y0.x, ci * acc[0].y + y0.y);
        float2 o1 = make_float2(ci * acc[1].x + y1.x, ci * acc[1].y + y1.y);
        float2 o2 = make_float2(ci * acc[2].x + y2.x, ci * acc[2].y + y2.y);
        float2 o3 = make_float2(ci * acc[3].x + y3.x, ci * acc[3].y + y3.y);
        uint4 o;
        *(__half2*)&o.x = __float22half2_rn(o0);
        *(__half2*)&o.y = __float22half2_rn(o1);
        *(__half2*)&o.z = __float22half2_rn(o2);
        *(__half2*)&o.w = __float22half2_rn(o3);
        *(uint4*)(nxt + (size_t)row * 128 + c) = o;
    }
}

// ---------------- tensor-core gate MLP + segment max ----------------
__global__ void __launch_bounds__(256)
k_gate_mma(const __half* __restrict__ h16, const __half* __restrict__ Wg1h,
           const float* __restrict__ bg1, const float* __restrict__ Wg2,
           const float* __restrict__ bg2, const void* bt) {
    extern __shared__ char smem_raw[];
    __half* sW = (__half*)smem_raw;        // [128][72]
    __half* sA = sW + 128 * 72;            // [128][136]
    float* sB  = (float*)(sA + 128 * 136); // 64
    float* sG2 = sB + 64;                  // 64

    int t = threadIdx.x;
    for (int i = t; i < 128 * 8; i += 256) {
        int r = i >> 3, ch = i & 7;
        *(uint4*)(sW + r * 72 + ch * 8) = *(const uint4*)(Wg1h + r * 64 + ch * 8);
    }
    if (t < 64) { sB[t] = bg1[t]; sG2[t] = Wg2[t]; }

    int nbase = blockIdx.x * 128;
    for (int i = t; i < 128 * 16; i += 256) {
        int r = i >> 4, ch = i & 15;
        int node = nbase + r;
        uint4 v = make_uint4(0, 0, 0, 0);
        if (node < NN) v = *(const uint4*)(h16 + (size_t)node * 128 + ch * 8);
        *(uint4*)(sA + r * 136 + ch * 8) = v;
    }
    __syncthreads();

    int warp = t >> 5, lane = t & 31;
    int mbase = warp * 16;
    uint32_t sA_b = (uint32_t)__cvta_generic_to_shared(sA);
    uint32_t sW_b = (uint32_t)__cvta_generic_to_shared(sW);

    float c[8][4];
#pragma unroll
    for (int nt = 0; nt < 8; nt++) { c[nt][0] = c[nt][1] = c[nt][2] = c[nt][3] = 0.f; }
#pragma unroll
    for (int ks = 0; ks < 8; ks++) {
        uint32_t a0, a1, a2, a3;
        uint32_t aaddr = sA_b +
            (((mbase + (lane & 15)) * 136 + ks * 16 + ((lane >> 4) << 3)) << 1);
        ldsm_x4(a0, a1, a2, a3, aaddr);
#pragma unroll
        for (int nt = 0; nt < 8; nt++) {
            uint32_t b0, b1;
            uint32_t baddr = sW_b + (((ks * 16 + (lane & 15)) * 72 + nt * 8) << 1);
            ldsm_x2t(b0, b1, baddr);
            mma16816(c[nt], a0, a1, a2, a3, b0, b1);
        }
    }

    float p0 = 0.f, p1 = 0.f;
#pragma unroll
    for (int nt = 0; nt < 8; nt++) {
        int col0 = nt * 8 + (lane & 3) * 2;
        p0 += gelu(c[nt][0] + sB[col0]) * sG2[col0]
            + gelu(c[nt][1] + sB[col0 + 1]) * sG2[col0 + 1];
        p1 += gelu(c[nt][2] + sB[col0]) * sG2[col0]
            + gelu(c[nt][3] + sB[col0 + 1]) * sG2[col0 + 1];
    }
    p0 += __shfl_xor_sync(~0u, p0, 1); p0 += __shfl_xor_sync(~0u, p0, 2);
    p1 += __shfl_xor_sync(~0u, p1, 1); p1 += __shfl_xor_sync(~0u, p1, 2);

    if ((lane & 3) == 0) {
        int r0 = lane >> 2;
        float b2 = bg2[0];
        int is64 = g_is64b;
        int n0 = nbase + mbase + r0;
        int n1 = n0 + 8;
        if (n0 < NN) {
            float g = p0 + b2;
            g_gate[n0] = g;
            atomicMaxF(&g_bmax[ldidx(bt, is64, n0)], g);
        }
        if (n1 < NN) {
            float g = p1 + b2;
            g_gate[n1] = g;
            atomicMaxF(&g_bmax[ldidx(bt, is64, n1)], g);
        }
    }
}

// ---------------- pooling: exp + weighted sum + bsum, fused ----------------
#define GCHUNK 256
__global__ void __launch_bounds__(128) k_gagg(const __half* __restrict__ h16,
                                              float* __restrict__ outg,
                                              const void* bt) {
    int j = threadIdx.x;
    int base = blockIdx.x * GCHUNK;
    int lim = base + GCHUNK;
    if (lim > NN) lim = NN;
    int is64 = g_is64b;
    float acc = 0.f, esum = 0.f;
    int curb = -1;
    float bmax = 0.f;
    for (int n = base; n < lim; n++) {
        int b = ldidx(bt, is64, n);
        if (b != curb) {
            if (curb >= 0) {
                atomicAdd(&outg[curb * 128 + j], acc);
                if (j == 0) atomicAdd(&g_bsum[curb], esum);
            }
            curb = b;
            acc = 0.f; esum = 0.f;
            bmax = g_bmax[b];
        }
        float e = expf(g_gate[n] - bmax);
        acc += e * __half2float(h16[(size_t)n * 128 + j]);
        if (j == 0) esum += e;
    }
    if (curb >= 0) {
        atomicAdd(&outg[curb * 128 + j], acc);
        if (j == 0) atomicAdd(&g_bsum[curb], esum);
    }
}

__global__ void k_gdiv(float* __restrict__ outg) {
    int i = blockIdx.x * blockDim.x + threadIdx.x;
    if (i >= BB * 128) return;
    float s = g_bsum[i >> 7];
    if (s > 0.f) outg[i] /= s;
}

// ---------------- launch ----------------
extern "C" void kernel_launch(void* const* d_in, const int* in_sizes, int n_in,
                              void* d_out, int out_size) {
    const float* x = (const float*)d_in[0];
    const void* ei = d_in[1];
    const void* bt = d_in[2];
    const float* ea = (const float*)d_in[3];
    const float* We1 = (const float*)d_in[4];  const float* be1 = (const float*)d_in[5];
    const float* W1a = (const float*)d_in[6];  const float* b1a = (const float*)d_in[7];
    const float* W1b = (const float*)d_in[8];  const float* b1b = (const float*)d_in[9];
    const float* g1  = (const float*)d_in[10]; const float* bn1 = (const float*)d_in[11];
    const float* We2 = (const float*)d_in[12]; const float* be2 = (const float*)d_in[13];
    const float* W2a = (const float*)d_in[14]; const float* b2a = (const float*)d_in[15];
    const float* W2b = (const float*)d_in[16]; const float* b2b = (const float*)d_in[17];
    const float* g2  = (const float*)d_in[18]; const float* bn2 = (const float*)d_in[19];
    const float* Wg1 = (const float*)d_in[20]; const float* bg1 = (const float*)d_in[21];
    const float* Wg2 = (const float*)d_in[22]; const float* bg2 = (const float*)d_in[23];

    float* outh = (float*)d_out;
    float* outg = outh + (size_t)NN * 128;

    __half *pT0h, *pHBh, *pA16, *pB16, *pX0h, *pW1ah, *pW1bh, *pW2ah, *pW2bh, *pWg1h;
    cudaGetSymbolAddress((void**)&pT0h, g_t0h);
    cudaGetSymbolAddress((void**)&pHBh, g_hBh);
    cudaGetSymbolAddress((void**)&pA16, g_h16A);
    cudaGetSymbolAddress((void**)&pB16, g_h16B);
    cudaGetSymbolAddress((void**)&pX0h, g_x0h);
    cudaGetSymbolAddress((void**)&pW1ah, g_w1ah);
    cudaGetSymbolAddress((void**)&pW1bh, g_w1bh);
    cudaGetSymbolAddress((void**)&pW2ah, g_w2ah);
    cudaGetSymbolAddress((void**)&pW2bh, g_w2bh);
    cudaGetSymbolAddress((void**)&pWg1h, g_wg1h);

    size_t sz1 = (size_t)(64 * 136 + 128 * 136 + 128 * 72 + 128 * 136) * 2 + 4 * 128 * 4;
    size_t sz2 = (size_t)(128 * 136 + 128 * 136 + 128 * 136 + 128 * 136) * 2 + 4 * 128 * 4;
    size_t szg = (size_t)(128 * 72 + 128 * 136) * 2 + 2 * 64 * 4;
    cudaFuncSetAttribute(k_mlp_mma<64, 1, 0>, cudaFuncAttributeMaxDynamicSharedMemorySize, (int)sz1);
    cudaFuncSetAttribute(k_mlp_mma<128, 0, 1>, cudaFuncAttributeMaxDynamicSharedMemorySize, (int)sz2);
    cudaFuncSetAttribute(k_gate_mma, cudaFuncAttributeMaxDynamicSharedMemorySize, (int)szg);

    k_detect<<<1, 256>>>((const unsigned*)ei, (const unsigned*)bt);
    k_init<<<(NN * 32 + 255) / 256, 256>>>(outg, x);
    k_cvtw<<<64, 256>>>(W1a, W1b, W2a, W2b, Wg1);
    k_hist<<<(EE + 255) / 256, 256>>>(ei);
    k_scan_sum<<<SNB, 256>>>();
    k_scan_part<<<1, 32>>>();
    k_scan_write<<<SNB, 1024>>>();
    k_build<<<(EE + 255) / 256, 256>>>(ei, ea);

    int ntile = (NN + 127) / 128;
    int pair_blocks = ((NN + 1) / 2 * 32 + 255) / 256;
    k_conv1<<<(NN * 32 + 255) / 256, 256>>>(x, We1, be1);
    k_mlp_mma<64, 1, 0><<<ntile, 256, sz1>>>(pT0h, pA16, pW1ah, b1a, pW1bh, b1b, g1, bn1,
                                             nullptr, nullptr);
    k_conv2<<<pair_blocks, 256>>>(pA16, pHBh, We2, be2);
    // mlp2: in=pHBh, out=x0h, fused prep: u0 -> pA16, y0 -> pB16
    k_mlp_mma<128, 0, 1><<<ntile, 256, sz2>>>(pHBh, pX0h, pW2ah, b2a, pW2bh, b2b, g2, bn2,
                                              pA16, pB16);

    // APPNP: u ping-pong pA16 <-> pHBh, y0 in pB16
    const __half* cur = pA16;
    for (int it = 0; it < 15; it++) {
        __half* nxt = (it & 1) ? pA16 : pHBh;
        k_appnp16<0><<<pair_blocks, 256>>>(cur, nxt, nullptr, pB16, pX0h);
        cur = nxt;
    }
    // final (it15): cur=pHBh; fp32 outh + fp16 h copy into pA16
    k_appnp16<1><<<pair_blocks, 256>>>(cur, pA16, outh, pB16, pX0h);

    k_gate_mma<<<ntile, 256, szg>>>(pA16, pWg1h, bg1, Wg2, bg2, bt);
    k_gagg<<<(NN + GCHUNK - 1) / GCHUNK, 128>>>(pA16, outg, bt);
    k_gdiv<<<(BB * 128 + 255) / 256, 256>>>(outg);
}

// round 17
// speedup vs baseline: 1.2516x; 1.0523x over previous
#include <cuda_runtime.h>
#include <cuda_fp16.h>
#include <math.h>
#include <stdint.h>

#define NN 100000
#define EE 1600000
#define BB 64
#define LN_EPS 1e-5f

// ---------------- scratch ----------------
static __device__ int    g_deg[NN];
static __device__ int    g_rowstart[NN + 1];
static __device__ int    g_wptr[NN];
static __device__ float  g_dis[NN];
static __device__ float  g_selfw[NN];
static __device__ int2   g_edge8[EE];         // {src, half2(ea0,ea1)} (convs)
static __device__ int    g_esrc[EE];          // src only (APPNP)
static __device__ __half g_x16[NN * 64];
static __device__ __half g_t0h[NN * 64];
static __device__ __half g_hBh[NN * 128];     // conv2 out -> mlp2 in -> APPNP pong
static __device__ __half g_h16A[NN * 128];    // u ping
static __device__ __half g_h16B[NN * 128];    // y0
static __device__ __half g_x0h[NN * 128];     // mlp2 out (h0 = x0), kept intact
static __device__ __half g_w1ah[64 * 128];
static __device__ __half g_w1bh[128 * 128];
static __device__ __half g_w2ah[128 * 128];
static __device__ __half g_w2bh[128 * 128];
static __device__ __half g_wg1h[128 * 64];
static __device__ float  g_gate[NN];
static __device__ float  g_bmax[BB];
static __device__ float  g_bsum[BB];
static __device__ int    g_part[64];
static __device__ int    g_is64e, g_is64b;

// ---------------- helpers ----------------
__device__ __forceinline__ int ldidx(const void* p, int is64, long long i) {
    if (is64) return (int)((const long long*)p)[i];
    return ((const int*)p)[i];
}

__device__ __forceinline__ float gelu(float x) {
    return 0.5f * x * (1.0f + erff(x * 0.70710678118654752440f));
}

__device__ __forceinline__ void atomicMaxF(float* a, float v) {
    int* ai = (int*)a;
    int old = *ai;
    while (__int_as_float(old) < v) {
        int assumed = old;
        old = atomicCAS(ai, assumed, __float_as_int(v));
        if (old == assumed) break;
    }
}

__device__ __forceinline__ void add8(float2 a[4], uint4 v) {
    float2 f0 = __half22float2(*(__half2*)&v.x);
    float2 f1 = __half22float2(*(__half2*)&v.y);
    float2 f2 = __half22float2(*(__half2*)&v.z);
    float2 f3 = __half22float2(*(__half2*)&v.w);
    a[0].x += f0.x; a[0].y += f0.y;
    a[1].x += f1.x; a[1].y += f1.y;
    a[2].x += f2.x; a[2].y += f2.y;
    a[3].x += f3.x; a[3].y += f3.y;
}

// ---- mma primitives ----
__device__ __forceinline__ void ldsm_x4(uint32_t& a0, uint32_t& a1, uint32_t& a2,
                                        uint32_t& a3, uint32_t addr) {
    asm volatile("ldmatrix.sync.aligned.m8n8.x4.shared.b16 {%0,%1,%2,%3},[%4];\n"
                 : "=r"(a0), "=r"(a1), "=r"(a2), "=r"(a3) : "r"(addr));
}
__device__ __forceinline__ void ldsm_x2t(uint32_t& b0, uint32_t& b1, uint32_t addr) {
    asm volatile("ldmatrix.sync.aligned.m8n8.x2.trans.shared.b16 {%0,%1},[%2];\n"
                 : "=r"(b0), "=r"(b1) : "r"(addr));
}
__device__ __forceinline__ void mma16816(float* c, uint32_t a0, uint32_t a1, uint32_t a2,
                                         uint32_t a3, uint32_t b0, uint32_t b1) {
    asm volatile(
        "mma.sync.aligned.m16n8k16.row.col.f32.f16.f16.f32 "
        "{%0,%1,%2,%3},{%4,%5,%6,%7},{%8,%9},{%0,%1,%2,%3};\n"
        : "+f"(c[0]), "+f"(c[1]), "+f"(c[2]), "+f"(c[3])
        : "r"(a0), "r"(a1), "r"(a2), "r"(a3), "r"(b0), "r"(b1));
}

// ---------------- fused init: detect dtype + zero counters + x->fp16 + cvt weights ---
__global__ void k_init(float* outg, const float* __restrict__ x,
                       const unsigned* __restrict__ ei, const unsigned* __restrict__ bt,
                       const float* __restrict__ W1a, const float* __restrict__ W1b,
                       const float* __restrict__ W2a, const float* __restrict__ W2b,
                       const float* __restrict__ Wg1) {
    int i = blockIdx.x * blockDim.x + threadIdx.x;
    // --- block 0: dtype detection (tail-region odd-word OR) ---
    if (blockIdx.x == 0) {
        __shared__ unsigned s1[256], s2[256];
        int t = threadIdx.x;
        unsigned o1 = 0, o2 = 0;
        for (int k = t; k < 2048; k += 256) {
            o1 |= ei[(long long)2 * EE - 4096 + 2 * k + 1];
            o2 |= bt[NN - 4096 + 2 * k + 1];
        }
        s1[t] = o1; s2[t] = o2;
        __syncthreads();
        for (int o = 128; o; o >>= 1) {
            if (t < o) { s1[t] |= s1[t + o]; s2[t] |= s2[t + o]; }
            __syncthreads();
        }
        if (t == 0) { g_is64e = (s1[0] == 0); g_is64b = (s2[0] == 0); }
    }
    // --- elementwise init ---
    if (i < NN) g_deg[i] = 0;
    if (i < BB) { g_bmax[i] = __int_as_float(0xff800000); g_bsum[i] = 0.f; }
    if (i < BB * 128) outg[i] = 0.f;
    if (i == 0) g_rowstart[NN] = EE;
    if (i < NN * 32) {
        float2 v = ((const float2*)x)[i];
        ((__half2*)g_x16)[i] = __float22half2_rn(v);
    }
    // --- weight conversion ---
    if (i < 64 * 128) g_w1ah[i] = __float2half(W1a[i]);
    if (i < 128 * 64) g_wg1h[i] = __float2half(Wg1[i]);
    if (i < 128 * 128) {
        g_w1bh[i] = __float2half(W1b[i]);
        g_w2ah[i] = __float2half(W2a[i]);
        g_w2bh[i] = __float2half(W2b[i]);
    }
}

// ---------------- degree histogram ----------------
__global__ void k_hist(const void* ei) {
    int e = blockIdx.x * blockDim.x + threadIdx.x;
    if (e >= EE) return;
    int d = ldidx(ei, g_is64e, (long long)EE + e);
    atomicAdd(&g_deg[d], 1);
}

// ---------------- 3-phase exclusive scan ----------------
#define SCHUNK 8192
#define SNB 13

__global__ void k_scan_sum() {
    __shared__ int sh[8];
    int b = blockIdx.x, t = threadIdx.x;
    int base = b * SCHUNK, s = 0;
    for (int i = t; i < SCHUNK; i += 256) {
        int idx = base + i;
        if (idx < NN) s += g_deg[idx];
    }
    for (int o = 16; o; o >>= 1) s += __shfl_xor_sync(~0u, s, o);
    if ((t & 31) == 0) sh[t >> 5] = s;
    __syncthreads();
    if (t == 0) {
        int v = 0;
        for (int i = 0; i < 8; i++) v += sh[i];
        g_part[b] = v;
    }
}

__global__ void k_scan_part() {
    if (threadIdx.x == 0) {
        int r = 0;
        for (int i = 0; i < SNB; i++) { int v = g_part[i]; g_part[i] = r; r += v; }
    }
}

__global__ void k_scan_write() {
    __shared__ int sh[1024];
    int b = blockIdx.x, t = threadIdx.x;
    int base = b * SCHUNK + t * 8;
    int loc[8];
    int s = 0;
#pragma unroll
    for (int j = 0; j < 8; j++) {
        int idx = base + j;
        int v = (idx < NN) ? g_deg[idx] : 0;
        loc[j] = s; s += v;
    }
    sh[t] = s;
    __syncthreads();
    for (int off = 1; off < 1024; off <<= 1) {
        int v = (t >= off) ? sh[t - off] : 0;
        __syncthreads();
        sh[t] += v;
        __syncthreads();
    }
    int off0 = g_part[b] + sh[t] - s;
#pragma unroll
    for (int j = 0; j < 8; j++) {
        int idx = base + j;
        if (idx < NN) {
            int rs = off0 + loc[j];
            g_rowstart[idx] = rs;
            g_wptr[idx] = rs;
            int d = g_deg[idx] + 1;
            g_dis[idx] = rsqrtf((float)d);
            g_selfw[idx] = 1.0f / (float)d;
        }
    }
}

// ---------------- CSR build (slim records) ----------------
__global__ void k_build(const void* ei, const float* __restrict__ ea) {
    int e = blockIdx.x * blockDim.x + threadIdx.x;
    if (e >= EE) return;
    int is64 = g_is64e;
    int s = ldidx(ei, is64, e);
    int d = ldidx(ei, is64, (long long)EE + e);
    int pos = atomicAdd(&g_wptr[d], 1);
    float2 a = ((const float2*)ea)[e];
    __half2 ah = __float22half2_rn(a);
    int2 rec;
    rec.x = s;
    rec.y = *(int*)&ah;
    g_edge8[pos] = rec;
    g_esrc[pos] = s;
}

// ---------------- conv1 (64-dim, warp per dst, unroll 2, slim records) ----------------
__global__ void __launch_bounds__(256) k_conv1(const float* __restrict__ We1,
                                               const float* __restrict__ be1) {
    int gt = blockIdx.x * blockDim.x + threadIdx.x;
    int row = gt >> 5;
    if (row >= NN) return;
    int lane = gt & 31, c = 2 * lane;
    float w0x = We1[c], w0y = We1[c + 1];
    float w1x = We1[64 + c], w1y = We1[64 + c + 1];
    float bx = be1[c], by = be1[c + 1];
    int beg = g_rowstart[row], end = g_rowstart[row + 1];
    float ax = 0.f, ay = 0.f;
    int p = beg;
    for (; p + 2 <= end; p += 2) {
        int2 r0 = g_edge8[p];
        int2 r1 = g_edge8[p + 1];
        float2 e0 = __half22float2(*(__half2*)&r0.y);
        float2 e1 = __half22float2(*(__half2*)&r1.y);
        float2 xv0 = __half22float2(*(const __half2*)(g_x16 + (size_t)r0.x * 64 + c));
        float2 xv1 = __half22float2(*(const __half2*)(g_x16 + (size_t)r1.x * 64 + c));
        ax += fmaxf(xv0.x + e0.x * w0x + e0.y * w1x + bx, 0.f);
        ay += fmaxf(xv0.y + e0.x * w0y + e0.y * w1y + by, 0.f);
        ax += fmaxf(xv1.x + e1.x * w0x + e1.y * w1x + bx, 0.f);
        ay += fmaxf(xv1.y + e1.x * w0y + e1.y * w1y + by, 0.f);
    }
    if (p < end) {
        int2 r = g_edge8[p];
        float2 e0 = __half22float2(*(__half2*)&r.y);
        float2 xv = __half22float2(*(const __half2*)(g_x16 + (size_t)r.x * 64 + c));
        ax += fmaxf(xv.x + e0.x * w0x + e0.y * w1x + bx, 0.f);
        ay += fmaxf(xv.y + e0.x * w0y + e0.y * w1y + by, 0.f);
    }
    float2 xd = __half22float2(*(const __half2*)(g_x16 + (size_t)row * 64 + c));
    *(__half2*)(g_t0h + (size_t)row * 64 + c) =
        __float22half2_rn(make_float2(ax + xd.x, ay + xd.y));
}

// ---------------- conv2 (128-dim, 2 rows/warp, unroll 2, slim records) ----------------
__global__ void __launch_bounds__(256) k_conv2(const __half* __restrict__ hin,
                                               __half* __restrict__ hout,
                                               const float* __restrict__ We2,
                                               const float* __restrict__ be2) {
    int gwarp = (blockIdx.x * blockDim.x + threadIdx.x) >> 5;
    int lane = threadIdx.x & 31;
    int row = gwarp * 2 + (lane >> 4);
    if (row >= NN) return;
    int li = lane & 15, c = li * 8;
    float4 w0a = *(const float4*)(We2 + c);
    float4 w0b = *(const float4*)(We2 + c + 4);
    float4 w1a = *(const float4*)(We2 + 128 + c);
    float4 w1b = *(const float4*)(We2 + 128 + c + 4);
    float4 bva = *(const float4*)(be2 + c);
    float4 bvb = *(const float4*)(be2 + c + 4);
    int beg = g_rowstart[row], end = g_rowstart[row + 1];
    float2 acc[4] = {{0.f, 0.f}, {0.f, 0.f}, {0.f, 0.f}, {0.f, 0.f}};

#define C2_BODY(ez, ew, vv)                                                   \
    {                                                                         \
        float2 f0 = __half22float2(*(__half2*)&(vv).x);                       \
        float2 f1 = __half22float2(*(__half2*)&(vv).y);                       \
        float2 f2 = __half22float2(*(__half2*)&(vv).z);                       \
        float2 f3 = __half22float2(*(__half2*)&(vv).w);                       \
        acc[0].x += fmaxf(f0.x + (ez) * w0a.x + (ew) * w1a.x + bva.x, 0.f);   \
        acc[0].y += fmaxf(f0.y + (ez) * w0a.y + (ew) * w1a.y + bva.y, 0.f);   \
        acc[1].x += fmaxf(f1.x + (ez) * w0a.z + (ew) * w1a.z + bva.z, 0.f);   \
        acc[1].y += fmaxf(f1.y + (ez) * w0a.w + (ew) * w1a.w + bva.w, 0.f);   \
        acc[2].x += fmaxf(f2.x + (ez) * w0b.x + (ew) * w1b.x + bvb.x, 0.f);   \
        acc[2].y += fmaxf(f2.y + (ez) * w0b.y + (ew) * w1b.y + bvb.y, 0.f);   \
        acc[3].x += fmaxf(f3.x + (ez) * w0b.z + (ew) * w1b.z + bvb.z, 0.f);   \
        acc[3].y += fmaxf(f3.y + (ez) * w0b.w + (ew) * w1b.w + bvb.w, 0.f);   \
    }

    int p = beg;
    for (; p + 2 <= end; p += 2) {
        int2 r0 = g_edge8[p];
        int2 r1 = g_edge8[p + 1];
        float2 e0 = __half22float2(*(__half2*)&r0.y);
        float2 e1 = __half22float2(*(__half2*)&r1.y);
        uint4 v0 = *(const uint4*)(hin + (size_t)r0.x * 128 + c);
        uint4 v1 = *(const uint4*)(hin + (size_t)r1.x * 128 + c);
        C2_BODY(e0.x, e0.y, v0);
        C2_BODY(e1.x, e1.y, v1);
    }
    if (p < end) {
        int2 r = g_edge8[p];
        float2 e0 = __half22float2(*(__half2*)&r.y);
        uint4 v = *(const uint4*)(hin + (size_t)r.x * 128 + c);
        C2_BODY(e0.x, e0.y, v);
    }
#undef C2_BODY
    uint4 hd = *(const uint4*)(hin + (size_t)row * 128 + c);
    float2 d0 = __half22float2(*(__half2*)&hd.x);
    float2 d1 = __half22float2(*(__half2*)&hd.y);
    float2 d2 = __half22float2(*(__half2*)&hd.z);
    float2 d3 = __half22float2(*(__half2*)&hd.w);
    uint4 o;
    *(__half2*)&o.x = __float22half2_rn(make_float2(d0.x + acc[0].x, d0.y + acc[0].y));
    *(__half2*)&o.y = __float22half2_rn(make_float2(d1.x + acc[1].x, d1.y + acc[1].y));
    *(__half2*)&o.z = __float22half2_rn(make_float2(d2.x + acc[2].x, d2.y + acc[2].y));
    *(__half2*)&o.w = __float22half2_rn(make_float2(d3.x + acc[3].x, d3.y + acc[3].y));
    *(uint4*)(hout + (size_t)row * 128 + c) = o;
}

// ---------------- tensor-core fused MLP(+GELU)+LayerNorm (+optional APPNP prep) ------
template <int K1, int GELU_OUT, int PREP>
__global__ void __launch_bounds__(256)
k_mlp_mma(const __half* __restrict__ in, __half* __restrict__ out,
          const __half* __restrict__ Wah, const float* __restrict__ ba,
          const __half* __restrict__ Wbh, const float* __restrict__ bb,
          const float* __restrict__ gamma, const float* __restrict__ beta,
          __half* __restrict__ u0b, __half* __restrict__ y0b) {
    extern __shared__ char smem_raw[];
    constexpr int SA_STRIDE = K1 + 8;
    __half* sWa = (__half*)smem_raw;
    __half* sWb = sWa + K1 * 136;
    __half* sA  = sWb + 128 * 136;
    __half* sU  = sA + 128 * SA_STRIDE;
    float* sBa = (float*)(sU + 128 * 136);
    float* sBb = sBa + 128;
    float* sGm = sBb + 128;
    float* sBt = sGm + 128;

    int t = threadIdx.x;
    for (int i = t; i < K1 * 16; i += 256) {
        int r = i >> 4, ch = i & 15;
        *(uint4*)(sWa + r * 136 + ch * 8) = *(const uint4*)(Wah + r * 128 + ch * 8);
    }
    for (int i = t; i < 128 * 16; i += 256) {
        int r = i >> 4, ch = i & 15;
        *(uint4*)(sWb + r * 136 + ch * 8) = *(const uint4*)(Wbh + r * 128 + ch * 8);
    }
    if (t < 128) { sBa[t] = ba[t]; sBb[t] = bb[t]; sGm[t] = gamma[t]; sBt[t] = beta[t]; }

    int nbase = blockIdx.x * 128;
    constexpr int CH = K1 / 8;
    for (int i = t; i < 128 * CH; i += 256) {
        int r = i / CH, ch = i % CH;
        int node = nbase + r;
        uint4 v = make_uint4(0, 0, 0, 0);
        if (node < NN) v = *(const uint4*)(in + (size_t)node * K1 + ch * 8);
        *(uint4*)(sA + r * SA_STRIDE + ch * 8) = v;
    }
    __syncthreads();

    int warp = t >> 5, lane = t & 31;
    int mbase = warp * 16;
    uint32_t sA_b = (uint32_t)__cvta_generic_to_shared(sA);
    uint32_t sWa_b = (uint32_t)__cvta_generic_to_shared(sWa);
    uint32_t sWb_b = (uint32_t)__cvta_generic_to_shared(sWb);

    float c[16][4];

#pragma unroll
    for (int nt = 0; nt < 16; nt++) { c[nt][0] = c[nt][1] = c[nt][2] = c[nt][3] = 0.f; }
#pragma unroll
    for (int ks = 0; ks < K1 / 16; ks++) {
        uint32_t a0, a1, a2, a3;
        uint32_t aaddr = sA_b +
            (((mbase + (lane & 15)) * SA_STRIDE + ks * 16 + ((lane >> 4) << 3)) << 1);
        ldsm_x4(a0, a1, a2, a3, aaddr);
#pragma unroll
        for (int nt = 0; nt < 16; nt++) {
            uint32_t b0, b1;
            uint32_t baddr = sWa_b + (((ks * 16 + (lane & 15)) * 136 + nt * 8) << 1);
            ldsm_x2t(b0, b1, baddr);
            mma16816(c[nt], a0, a1, a2, a3, b0, b1);
        }
    }
    {
        int r0 = lane >> 2;
#pragma unroll
        for (int nt = 0; nt < 16; nt++) {
            int col0 = nt * 8 + (lane & 3) * 2;
            float u00 = gelu(c[nt][0] + sBa[col0]);
            float u01 = gelu(c[nt][1] + sBa[col0 + 1]);
            float u10 = gelu(c[nt][2] + sBa[col0]);
            float u11 = gelu(c[nt][3] + sBa[col0 + 1]);
            *(__half2*)(sU + (mbase + r0) * 136 + col0) =
                __float22half2_rn(make_float2(u00, u01));
            *(__half2*)(sU + (mbase + r0 + 8) * 136 + col0) =
                __float22half2_rn(make_float2(u10, u11));
        }
    }
    __syncwarp();
    uint32_t sU_b = (uint32_t)__cvta_generic_to_shared(sU);

#pragma unroll
    for (int nt = 0; nt < 16; nt++) { c[nt][0] = c[nt][1] = c[nt][2] = c[nt][3] = 0.f; }
#pragma unroll
    for (int ks = 0; ks < 8; ks++) {
        uint32_t a0, a1, a2, a3;
        uint32_t aaddr = sU_b +
            (((mbase + (lane & 15)) * 136 + ks * 16 + ((lane >> 4) << 3)) << 1);
        ldsm_x4(a0, a1, a2, a3, aaddr);
#pragma unroll
        for (int nt = 0; nt < 16; nt++) {
            uint32_t b0, b1;
            uint32_t baddr = sWb_b + (((ks * 16 + (lane & 15)) * 136 + nt * 8) << 1);
            ldsm_x2t(b0, b1, baddr);
            mma16816(c[nt], a0, a1, a2, a3, b0, b1);
        }
    }

    {
        int r0 = lane >> 2;
        float s0 = 0.f, q0 = 0.f, s1 = 0.f, q1 = 0.f;
#pragma unroll
        for (int nt = 0; nt < 16; nt++) {
            int col0 = nt * 8 + (lane & 3) * 2;
            float y00 = c[nt][0] + sBb[col0];
            float y01 = c[nt][1] + sBb[col0 + 1];
            float y10 = c[nt][2] + sBb[col0];
            float y11 = c[nt][3] + sBb[col0 + 1];
            if (GELU_OUT) { y00 = gelu(y00); y01 = gelu(y01); y10 = gelu(y10); y11 = gelu(y11); }
            c[nt][0] = y00; c[nt][1] = y01; c[nt][2] = y10; c[nt][3] = y11;
            s0 += y00 + y01; q0 += y00 * y00 + y01 * y01;
            s1 += y10 + y11; q1 += y10 * y10 + y11 * y11;
        }
#pragma unroll
        for (int o = 1; o <= 2; o <<= 1) {
            s0 += __shfl_xor_sync(~0u, s0, o); q0 += __shfl_xor_sync(~0u, q0, o);
            s1 += __shfl_xor_sync(~0u, s1, o); q1 += __shfl_xor_sync(~0u, q1, o);
        }
        float mu0 = s0 * (1.f / 128.f);
        float inv0 = rsqrtf(q0 * (1.f / 128.f) - mu0 * mu0 + LN_EPS);
        float mu1 = s1 * (1.f / 128.f);
        float inv1 = rsqrtf(q1 * (1.f / 128.f) - mu1 * mu1 + LN_EPS);
        int node0 = nbase + mbase + r0;
        int node1 = node0 + 8;
        float dis0 = 0.f, dis1 = 0.f;
        if (PREP) {
            if (node0 < NN) dis0 = g_dis[node0];
            if (node1 < NN) dis1 = g_dis[node1];
        }
#pragma unroll
        for (int nt = 0; nt < 16; nt++) {
            int col0 = nt * 8 + (lane & 3) * 2;
            float gm0 = sGm[col0], gm1 = sGm[col0 + 1];
            float bt0 = sBt[col0], bt1 = sBt[col0 + 1];
            if (node0 < NN) {
                float v0 = (c[nt][0] - mu0) * inv0 * gm0 + bt0;
                float v1 = (c[nt][1] - mu0) * inv0 * gm1 + bt1;
                *(__half2*)(out + (size_t)node0 * 128 + col0) =
                    __float22half2_rn(make_float2(v0, v1));
                if (PREP) {
                    float ua = dis0 * v0, ub = dis0 * v1;
                    *(__half2*)(u0b + (size_t)node0 * 128 + col0) =
                        __float22half2_rn(make_float2(ua, ub));
                    *(__half2*)(y0b + (size_t)node0 * 128 + col0) =
                        __float22half2_rn(make_float2(0.1f * ua, 0.1f * ub));
                }
            }
            if (node1 < NN) {
                float v0 = (c[nt][2] - mu1) * inv1 * gm0 + bt0;
                float v1 = (c[nt][3] - mu1) * inv1 * gm1 + bt1;
                *(__half2*)(out + (size_t)node1 * 128 + col0) =
                    __float22half2_rn(make_float2(v0, v1));
                if (PREP) {
                    float ua = dis1 * v0, ub = dis1 * v1;
                    *(__half2*)(u0b + (size_t)node1 * 128 + col0) =
                        __float22half2_rn(make_float2(ua, ub));
                    *(__half2*)(y0b + (size_t)node1 * 128 + col0) =
                        __float22half2_rn(make_float2(0.1f * ua, 0.1f * ub));
                }
            }
        }
    }
}

// ---------------- APPNP step on u-state (frozen config: 2 rows/warp, unroll 4) -------
template <int FINAL>
__global__ void __launch_bounds__(256) k_appnp16(const __half* __restrict__ cur,
                                                 __half* __restrict__ nxt,
                                                 float* __restrict__ outp,
                                                 const __half* __restrict__ y0h,
                                                 const __half* __restrict__ x0h) {
    int gwarp = (blockIdx.x * blockDim.x + threadIdx.x) >> 5;
    int lane = threadIdx.x & 31;
    int row = gwarp * 2 + (lane >> 4);
    if (row >= NN) return;
    int li = lane & 15, c = li * 8;
    int beg = g_rowstart[row], end = g_rowstart[row + 1];
    float2 acc[4] = {{0.f, 0.f}, {0.f, 0.f}, {0.f, 0.f}, {0.f, 0.f}};
    int p = beg;
    for (; p + 4 <= end; p += 4) {
        int s0 = g_esrc[p];
        int s1 = g_esrc[p + 1];
        int s2 = g_esrc[p + 2];
        int s3 = g_esrc[p + 3];
        uint4 v0 = *(const uint4*)(cur + (size_t)s0 * 128 + c);
        uint4 v1 = *(const uint4*)(cur + (size_t)s1 * 128 + c);
        uint4 v2 = *(const uint4*)(cur + (size_t)s2 * 128 + c);
        uint4 v3 = *(const uint4*)(cur + (size_t)s3 * 128 + c);
        add8(acc, v0);
        add8(acc, v1);
        add8(acc, v2);
        add8(acc, v3);
    }
    for (; p < end; p++) {
        int s = g_esrc[p];
        uint4 v = *(const uint4*)(cur + (size_t)s * 128 + c);
        add8(acc, v);
    }
    uint4 hd = *(const uint4*)(cur + (size_t)row * 128 + c);
    add8(acc, hd);  // + u_i

    if (FINAL) {
        float dis = g_dis[row];
        uint4 xv = *(const uint4*)(x0h + (size_t)row * 128 + c);
        float2 x0 = __half22float2(*(__half2*)&xv.x);
        float2 x1 = __half22float2(*(__half2*)&xv.y);
        float2 x2 = __half22float2(*(__half2*)&xv.z);
        float2 x3 = __half22float2(*(__half2*)&xv.w);
        float k = 0.9f * dis;
        float2 o0 = make_float2(k * acc[0].x + 0.1f * x0.x, k * acc[0].y + 0.1f * x0.y);
        float2 o1 = make_float2(k * acc[1].x + 0.1f * x1.x, k * acc[1].y + 0.1f * x1.y);
        float2 o2 = make_float2(k * acc[2].x + 0.1f * x2.x, k * acc[2].y + 0.1f * x2.y);
        float2 o3 = make_float2(k * acc[3].x + 0.1f * x3.x, k * acc[3].y + 0.1f * x3.y);
        float* op = outp + (size_t)row * 128 + c;
        *(float4*)op = make_float4(o0.x, o0.y, o1.x, o1.y);
        *(float4*)(op + 4) = make_float4(o2.x, o2.y, o3.x, o3.y);
        uint4 o;
        *(__half2*)&o.x = __float22half2_rn(o0);
        *(__half2*)&o.y = __float22half2_rn(o1);
        *(__half2*)&o.z = __float22half2_rn(o2);
        *(__half2*)&o.w = __float22half2_rn(o3);
        *(uint4*)(nxt + (size_t)row * 128 + c) = o;  // fp16 h copy for gate
    } else {
        float ci = 0.9f * g_selfw[row];
        uint4 yv = *(const uint4*)(y0h + (size_t)row * 128 + c);
        float2 y0 = __half22float2(*(__half2*)&yv.x);
        float2 y1 = __half22float2(*(__half2*)&yv.y);
        float2 y2 = __half22float2(*(__half2*)&yv.z);
        float2 y3 = __half22float2(*(__half2*)&yv.w);
        float2 o0 = make_float2(ci * acc[0].x + y0.x, ci * acc[0].y + y0.y);
        float2 o1 = make_float2(ci * acc[1].x + y1.x, ci * acc[1].y + y1.y);
        float2 o2 = make_float2(ci * acc[2].x + y2.x, ci * acc[2].y + y2.y);
        float2 o3 = make_float2(ci * acc[3].x + y3.x, ci * acc[3].y + y3.y);
        uint4 o;
        *(__half2*)&o.x = __float22half2_rn(o0);
        *(__half2*)&o.y = __float22half2_rn(o1);
        *(__half2*)&o.z = __float22half2_rn(o2);
        *(__half2*)&o.w = __float22half2_rn(o3);
        *(uint4*)(nxt + (size_t)row * 128 + c) = o;
    }
}

// ---------------- tensor-core gate MLP + segment max ----------------
__global__ void __launch_bounds__(256)
k_gate_mma(const __half* __restrict__ h16, const __half* __restrict__ Wg1h,
           const float* __restrict__ bg1, const float* __restrict__ Wg2,
           const float* __restrict__ bg2, const void* bt) {
    extern __shared__ char smem_raw[];
    __half* sW = (__half*)smem_raw;        // [128][72]
    __half* sA = sW + 128 * 72;            // [128][136]
    float* sB  = (float*)(sA + 128 * 136); // 64
    float* sG2 = sB + 64;                  // 64

    int t = threadIdx.x;
    for (int i = t; i < 128 * 8; i += 256) {
        int r = i >> 3, ch = i & 7;
        *(uint4*)(sW + r * 72 + ch * 8) = *(const uint4*)(Wg1h + r * 64 + ch * 8);
    }
    if (t < 64) { sB[t] = bg1[t]; sG2[t] = Wg2[t]; }

    int nbase = blockIdx.x * 128;
    for (int i = t; i < 128 * 16; i += 256) {
        int r = i >> 4, ch = i & 15;
        int node = nbase + r;
        uint4 v = make_uint4(0, 0, 0, 0);
        if (node < NN) v = *(const uint4*)(h16 + (size_t)node * 128 + ch * 8);
        *(uint4*)(sA + r * 136 + ch * 8) = v;
    }
    __syncthreads();

    int warp = t >> 5, lane = t & 31;
    int mbase = warp * 16;
    uint32_t sA_b = (uint32_t)__cvta_generic_to_shared(sA);
    uint32_t sW_b = (uint32_t)__cvta_generic_to_shared(sW);

    float c[8][4];
#pragma unroll
    for (int nt = 0; nt < 8; nt++) { c[nt][0] = c[nt][1] = c[nt][2] = c[nt][3] = 0.f; }
#pragma unroll
    for (int ks = 0; ks < 8; ks++) {
        uint32_t a0, a1, a2, a3;
        uint32_t aaddr = sA_b +
            (((mbase + (lane & 15)) * 136 + ks * 16 + ((lane >> 4) << 3)) << 1);
        ldsm_x4(a0, a1, a2, a3, aaddr);
#pragma unroll
        for (int nt = 0; nt < 8; nt++) {
            uint32_t b0, b1;
            uint32_t baddr = sW_b + (((ks * 16 + (lane & 15)) * 72 + nt * 8) << 1);
            ldsm_x2t(b0, b1, baddr);
            mma16816(c[nt], a0, a1, a2, a3, b0, b1);
        }
    }

    float p0 = 0.f, p1 = 0.f;
#pragma unroll
    for (int nt = 0; nt < 8; nt++) {
        int col0 = nt * 8 + (lane & 3) * 2;
        p0 += gelu(c[nt][0] + sB[col0]) * sG2[col0]
            + gelu(c[nt][1] + sB[col0 + 1]) * sG2[col0 + 1];
        p1 += gelu(c[nt][2] + sB[col0]) * sG2[col0]
            + gelu(c[nt][3] + sB[col0 + 1]) * sG2[col0 + 1];
    }
    p0 += __shfl_xor_sync(~0u, p0, 1); p0 += __shfl_xor_sync(~0u, p0, 2);
    p1 += __shfl_xor_sync(~0u, p1, 1); p1 += __shfl_xor_sync(~0u, p1, 2);

    if ((lane & 3) == 0) {
        int r0 = lane >> 2;
        float b2 = bg2[0];
        int is64 = g_is64b;
        int n0 = nbase + mbase + r0;
        int n1 = n0 + 8;
        if (n0 < NN) {
            float g = p0 + b2;
            g_gate[n0] = g;
            atomicMaxF(&g_bmax[ldidx(bt, is64, n0)], g);
        }
        if (n1 < NN) {
            float g = p1 + b2;
            g_gate[n1] = g;
            atomicMaxF(&g_bmax[ldidx(bt, is64, n1)], g);
        }
    }
}

// ---------------- pooling: exp + weighted sum + bsum, fused ----------------
#define GCHUNK 128
__global__ void __launch_bounds__(128) k_gagg(const __half* __restrict__ h16,
                                              float* __restrict__ outg,
                                              const void* bt) {
    int j = threadIdx.x;
    int base = blockIdx.x * GCHUNK;
    int lim = base + GCHUNK;
    if (lim > NN) lim = NN;
    int is64 = g_is64b;
    float acc = 0.f, esum = 0.f;
    int curb = -1;
    float bmax = 0.f;
    for (int n = base; n < lim; n++) {
        int b = ldidx(bt, is64, n);
        if (b != curb) {
            if (curb >= 0) {
                atomicAdd(&outg[curb * 128 + j], acc);
                if (j == 0) atomicAdd(&g_bsum[curb], esum);
            }
            curb = b;
            acc = 0.f; esum = 0.f;
            bmax = g_bmax[b];
        }
        float e = expf(g_gate[n] - bmax);
        acc += e * __half2float(h16[(size_t)n * 128 + j]);
        if (j == 0) esum += e;
    }
    if (curb >= 0) {
        atomicAdd(&outg[curb * 128 + j], acc);
        if (j == 0) atomicAdd(&g_bsum[curb], esum);
    }
}

__global__ void k_gdiv(float* __restrict__ outg) {
    int i = blockIdx.x * blockDim.x + threadIdx.x;
    if (i >= BB * 128) return;
    float s = g_bsum[i >> 7];
    if (s > 0.f) outg[i] /= s;
}

// ---------------- launch ----------------
extern "C" void kernel_launch(void* const* d_in, const int* in_sizes, int n_in,
                              void* d_out, int out_size) {
    const float* x = (const float*)d_in[0];
    const void* ei = d_in[1];
    const void* bt = d_in[2];
    const float* ea = (const float*)d_in[3];
    const float* We1 = (const float*)d_in[4];  const float* be1 = (const float*)d_in[5];
    const float* W1a = (const float*)d_in[6];  const float* b1a = (const float*)d_in[7];
    const float* W1b = (const float*)d_in[8];  const float* b1b = (const float*)d_in[9];
    const float* g1  = (const float*)d_in[10]; const float* bn1 = (const float*)d_in[11];
    const float* We2 = (const float*)d_in[12]; const float* be2 = (const float*)d_in[13];
    const float* W2a = (const float*)d_in[14]; const float* b2a = (const float*)d_in[15];
    const float* W2b = (const float*)d_in[16]; const float* b2b = (const float*)d_in[17];
    const float* g2  = (const float*)d_in[18]; const float* bn2 = (const float*)d_in[19];
    const float* Wg1 = (const float*)d_in[20]; const float* bg1 = (const float*)d_in[21];
    const float* Wg2 = (const float*)d_in[22]; const float* bg2 = (const float*)d_in[23];

    float* outh = (float*)d_out;
    float* outg = outh + (size_t)NN * 128;

    __half *pT0h, *pHBh, *pA16, *pB16, *pX0h, *pW1ah, *pW1bh, *pW2ah, *pW2bh, *pWg1h;
    cudaGetSymbolAddress((void**)&pT0h, g_t0h);
    cudaGetSymbolAddress((void**)&pHBh, g_hBh);
    cudaGetSymbolAddress((void**)&pA16, g_h16A);
    cudaGetSymbolAddress((void**)&pB16, g_h16B);
    cudaGetSymbolAddress((void**)&pX0h, g_x0h);
    cudaGetSymbolAddress((void**)&pW1ah, g_w1ah);
    cudaGetSymbolAddress((void**)&pW1bh, g_w1bh);
    cudaGetSymbolAddress((void**)&pW2ah, g_w2ah);
    cudaGetSymbolAddress((void**)&pW2bh, g_w2bh);
    cudaGetSymbolAddress((void**)&pWg1h, g_wg1h);

    size_t sz1 = (size_t)(64 * 136 + 128 * 136 + 128 * 72 + 128 * 136) * 2 + 4 * 128 * 4;
    size_t sz2 = (size_t)(128 * 136 + 128 * 136 + 128 * 136 + 128 * 136) * 2 + 4 * 128 * 4;
    size_t szg = (size_t)(128 * 72 + 128 * 136) * 2 + 2 * 64 * 4;
    cudaFuncSetAttribute(k_mlp_mma<64, 1, 0>, cudaFuncAttributeMaxDynamicSharedMemorySize, (int)sz1);
    cudaFuncSetAttribute(k_mlp_mma<128, 0, 1>, cudaFuncAttributeMaxDynamicSharedMemorySize, (int)sz2);
    cudaFuncSetAttribute(k_gate_mma, cudaFuncAttributeMaxDynamicSharedMemorySize, (int)szg);

    // fused init (detect + zero + x->fp16 + weight cvt)
    k_init<<<(NN * 32 + 255) / 256, 256>>>(outg, x, (const unsigned*)ei,
                                           (const unsigned*)bt, W1a, W1b, W2a, W2b, Wg1);
    k_hist<<<(EE + 255) / 256, 256>>>(ei);
    k_scan_sum<<<SNB, 256>>>();
    k_scan_part<<<1, 32>>>();
    k_scan_write<<<SNB, 1024>>>();
    k_build<<<(EE + 255) / 256, 256>>>(ei, ea);

    int ntile = (NN + 127) / 128;
    int pair_blocks = ((NN + 1) / 2 * 32 + 255) / 256;
    k_conv1<<<(NN * 32 + 255) / 256, 256>>>(We1, be1);
    k_mlp_mma<64, 1, 0><<<ntile, 256, sz1>>>(pT0h, pA16, pW1ah, b1a, pW1bh, b1b, g1, bn1,
                                             nullptr, nullptr);
    k_conv2<<<pair_blocks, 256>>>(pA16, pHBh, We2, be2);
    // mlp2: in=pHBh, out=x0h, fused prep: u0 -> pA16, y0 -> pB16
    k_mlp_mma<128, 0, 1><<<ntile, 256, sz2>>>(pHBh, pX0h, pW2ah, b2a, pW2bh, b2b, g2, bn2,
                                              pA16, pB16);

    // APPNP: u ping-pong pA16 <-> pHBh, y0 in pB16
    const __half* cur = pA16;
    for (int it = 0; it < 15; it++) {
        __half* nxt = (it & 1) ? pA16 : pHBh;
        k_appnp16<0><<<pair_blocks, 256>>>(cur, nxt, nullptr, pB16, pX0h);
        cur = nxt;
    }
    // final (it15): cur=pHBh; fp32 outh + fp16 h copy into pA16
    k_appnp16<1><<<pair_blocks, 256>>>(cur, pA16, outh, pB16, pX0h);

    k_gate_mma<<<ntile, 256, szg>>>(pA16, pWg1h, bg1, Wg2, bg2, bt);
    k_gagg<<<(NN + GCHUNK - 1) / GCHUNK, 128>>>(pA16, outg, bt);
    k_gdiv<<<(BB * 128 + 255) / 256, 256>>>(outg);
}